// round 1
// baseline (speedup 1.0000x reference)
#include <cuda_runtime.h>
#include <math.h>
#include <stdint.h>

#define DIMV   64
#define NG     512
#define NNODES 20000
#define NEDGES 60000
#define NFEAT  11
#define EHID   128
#define WE_COLS 4096   // DIM*DIM

// ---------------- scratch (__device__ globals; no allocations allowed) ----------------
__device__ float g_We[(size_t)NEDGES * WE_COLS];      // 983 MB
__device__ float g_hedge[NEDGES * EHID];              // 30.7 MB
__device__ float g_h[NNODES * DIMV];                  // node state (out == h)
__device__ float g_agg[NNODES * DIMV];
__device__ float g_m[NNODES * DIMV];
__device__ float g_gi[NNODES * 3 * DIMV];
__device__ float g_gh[NNODES * 3 * DIMV];
__device__ float g_invdeg[NNODES];
__device__ int   g_degi[NNODES];
__device__ int   g_cnt[NG];
__device__ int   g_gstart[NG + 1];
__device__ float g_ebuf[NNODES];
__device__ float g_qstar[NG * 2 * DIMV];
__device__ float g_hs[NG * DIMV];
__device__ float g_cs[NG * DIMV];

// ---------------- generic fp32 GEMM:  C = act(A[M,K] @ W[Nc,K]^T + bias + addend*rowscale) ----
#define BM 64
#define BN 64
#define BKK 16

__global__ void gemm_kernel(const float* __restrict__ A, const float* __restrict__ W,
                            const float* __restrict__ bias,
                            const float* __restrict__ addend, const float* __restrict__ rowscale,
                            float* __restrict__ C, int M, int Nc, int K, int do_relu)
{
    __shared__ float As[BKK][BM];
    __shared__ float Ws[BKK][BN];

    const int bm = blockIdx.y * BM;
    const int bn = blockIdx.x * BN;
    const int tid = threadIdx.x;           // 256 threads
    const int tm = (tid / 16) * 4;
    const int tn = (tid % 16) * 4;

    float acc[4][4];
#pragma unroll
    for (int i = 0; i < 4; i++)
#pragma unroll
        for (int j = 0; j < 4; j++) acc[i][j] = 0.f;

    for (int k0 = 0; k0 < K; k0 += BKK) {
        // load A tile (BM x BKK), store transposed As[k][m]
#pragma unroll
        for (int r = 0; r < 4; r++) {
            int idx = tid + r * 256;        // 0..1023
            int mm = idx / BKK, kk = idx % BKK;
            int gm = bm + mm, gk = k0 + kk;
            float v = 0.f;
            if (gm < M && gk < K) v = A[(size_t)gm * K + gk];
            As[kk][mm] = v;
        }
        // load W tile: Ws[k][n] = W[(bn+n)*K + k0+k]
#pragma unroll
        for (int r = 0; r < 4; r++) {
            int idx = tid + r * 256;
            int nn = idx / BKK, kk = idx % BKK;
            int gn = bn + nn, gk = k0 + kk;
            float v = 0.f;
            if (gn < Nc && gk < K) v = W[(size_t)gn * K + gk];
            Ws[kk][nn] = v;
        }
        __syncthreads();

#pragma unroll
        for (int kk = 0; kk < BKK; kk++) {
            float a0 = As[kk][tm + 0], a1 = As[kk][tm + 1], a2 = As[kk][tm + 2], a3 = As[kk][tm + 3];
            float b0 = Ws[kk][tn + 0], b1 = Ws[kk][tn + 1], b2 = Ws[kk][tn + 2], b3 = Ws[kk][tn + 3];
            acc[0][0] += a0 * b0; acc[0][1] += a0 * b1; acc[0][2] += a0 * b2; acc[0][3] += a0 * b3;
            acc[1][0] += a1 * b0; acc[1][1] += a1 * b1; acc[1][2] += a1 * b2; acc[1][3] += a1 * b3;
            acc[2][0] += a2 * b0; acc[2][1] += a2 * b1; acc[2][2] += a2 * b2; acc[2][3] += a2 * b3;
            acc[3][0] += a3 * b0; acc[3][1] += a3 * b1; acc[3][2] += a3 * b2; acc[3][3] += a3 * b3;
        }
        __syncthreads();
    }

#pragma unroll
    for (int i = 0; i < 4; i++) {
        int gm = bm + tm + i;
        if (gm >= M) continue;
        float rs = rowscale ? rowscale[gm] : 1.f;
#pragma unroll
        for (int j = 0; j < 4; j++) {
            int gn = bn + tn + j;
            if (gn >= Nc) continue;
            float v = acc[i][j];
            if (bias)   v += bias[gn];
            if (addend) v += addend[(size_t)gm * Nc + gn] * rs;
            if (do_relu) v = fmaxf(v, 0.f);
            C[(size_t)gm * Nc + gn] = v;
        }
    }
}

// ---------------- degree / batch bookkeeping ----------------
__global__ void count_deg_kernel(const int* __restrict__ ei, int E)
{
    int e = blockIdx.x * blockDim.x + threadIdx.x;
    if (e < E) atomicAdd(&g_degi[ei[E + e]], 1);
}

__global__ void count_batch_kernel(const int* __restrict__ batch, int N)
{
    int i = blockIdx.x * blockDim.x + threadIdx.x;
    if (i < N) atomicAdd(&g_cnt[batch[i]], 1);
}

__global__ void invdeg_kernel(int N)
{
    int i = blockIdx.x * blockDim.x + threadIdx.x;
    if (i < N) g_invdeg[i] = 1.f / fmaxf((float)g_degi[i], 1.f);
}

__global__ void scan_kernel()
{
    __shared__ int s[NG];
    int t = threadIdx.x;
    s[t] = g_cnt[t];
    __syncthreads();
    for (int off = 1; off < NG; off <<= 1) {
        int v = (t >= off) ? s[t - off] : 0;
        __syncthreads();
        s[t] += v;
        __syncthreads();
    }
    if (t == 0) g_gstart[0] = 0;
    g_gstart[t + 1] = s[t];
}

// ---------------- per-edge message + scatter:  agg[dst] += out[src] @ We[e] ----------------
__global__ void msg_kernel(const int* __restrict__ ei, int E)
{
    const int le = threadIdx.x >> 6;      // 4 edges per 256-thread block
    const int o  = threadIdx.x & 63;
    const int e  = blockIdx.x * 4 + le;
    __shared__ float s_out[4][DIMV];

    int dst = 0;
    if (e < E) {
        int src = ei[e];
        dst = ei[E + e];
        s_out[le][o] = g_h[src * DIMV + o];
    }
    __syncthreads();
    if (e >= E) return;

    const float* __restrict__ w = g_We + (size_t)e * WE_COLS + o;
    float acc = 0.f;
#pragma unroll
    for (int i = 0; i < DIMV; i++) acc += s_out[le][i] * w[i * DIMV];
    atomicAdd(&g_agg[dst * DIMV + o], acc);
}

// ---------------- GRU elementwise update (PyTorch r,z,n layout) ----------------
__global__ void gru_kernel(int N)
{
    int idx = blockIdx.x * blockDim.x + threadIdx.x;
    if (idx >= N * DIMV) return;
    int n = idx / DIMV, d = idx % DIMV;
    const float* gi = g_gi + (size_t)n * 3 * DIMV;
    const float* gh = g_gh + (size_t)n * 3 * DIMV;
    float ir = gi[d], iz = gi[DIMV + d], in_ = gi[2 * DIMV + d];
    float hr = gh[d], hz = gh[DIMV + d], hn  = gh[2 * DIMV + d];
    float r = 1.f / (1.f + expf(-(ir + hr)));
    float z = 1.f / (1.f + expf(-(iz + hz)));
    float nn = tanhf(in_ + r * hn);
    float h = g_h[idx];
    g_h[idx] = (1.f - z) * nn + z * h;
}

// ---------------- Set2Set LSTM step (one block per graph, 256 threads = 256 gates) ------------
__global__ void lstm_kernel(const float* __restrict__ w_ih, const float* __restrict__ w_hh,
                            const float* __restrict__ b_ih, const float* __restrict__ b_hh)
{
    int b = blockIdx.x, t = threadIdx.x;
    __shared__ float qs[2 * DIMV];
    __shared__ float hsh[DIMV];
    __shared__ float gates[4 * DIMV];
    if (t < 128) qs[t] = g_qstar[b * 128 + t];
    if (t < 64)  hsh[t] = g_hs[b * 64 + t];
    __syncthreads();

    float acc = b_ih[t] + b_hh[t];
    const float* wih = w_ih + (size_t)t * 128;
    const float* whh = w_hh + (size_t)t * 64;
#pragma unroll 8
    for (int k = 0; k < 128; k++) acc += qs[k] * wih[k];
#pragma unroll 8
    for (int k = 0; k < 64; k++)  acc += hsh[k] * whh[k];
    gates[t] = acc;
    __syncthreads();

    if (t < 64) {
        float i = 1.f / (1.f + expf(-gates[t]));
        float f = 1.f / (1.f + expf(-gates[64 + t]));
        float g = tanhf(gates[128 + t]);
        float o = 1.f / (1.f + expf(-gates[192 + t]));
        float c = f * g_cs[b * 64 + t] + i * g;
        g_cs[b * 64 + t] = c;
        g_hs[b * 64 + t] = o * tanhf(c);
    }
}

// ---------------- Set2Set attention (one block = one graph; batch is sorted) ------------------
__global__ void attn_kernel()
{
    int b = blockIdx.x, t = threadIdx.x;   // 64 threads
    int s = g_gstart[b], e_end = g_gstart[b + 1];
    __shared__ float q[DIMV];
    __shared__ float red[DIMV];
    q[t] = g_hs[b * DIMV + t];
    __syncthreads();

    // pass 1: e_n = <out_n, q>, track max
    float lmax = -1e30f;
    for (int n = s + t; n < e_end; n += 64) {
        const float* row = g_h + (size_t)n * DIMV;
        float acc = 0.f;
#pragma unroll 8
        for (int i = 0; i < DIMV; i++) acc += row[i] * q[i];
        g_ebuf[n] = acc;
        lmax = fmaxf(lmax, acc);
    }
    red[t] = lmax; __syncthreads();
    for (int st = 32; st > 0; st >>= 1) { if (t < st) red[t] = fmaxf(red[t], red[t + st]); __syncthreads(); }
    float gmax = red[0];
    __syncthreads();

    // pass 2: a_n = exp(e_n - max), sum
    float lsum = 0.f;
    for (int n = s + t; n < e_end; n += 64) {
        float a = expf(g_ebuf[n] - gmax);
        g_ebuf[n] = a;
        lsum += a;
    }
    red[t] = lsum; __syncthreads();
    for (int st = 32; st > 0; st >>= 1) { if (t < st) red[t] += red[t + st]; __syncthreads(); }
    float S = red[0];
    __syncthreads();

    // pass 3: r_t = sum_n a_n * out[n][t]  (coalesced over t)
    float r = 0.f;
    for (int n = s; n < e_end; n++) r += g_ebuf[n] * g_h[(size_t)n * DIMV + t];

    g_qstar[b * 128 + t] = q[t];
    g_qstar[b * 128 + 64 + t] = (e_end > s) ? (r / S) : 0.f;
}

// ---------------- readout: y = relu(q_star @ lin1^T + b1) @ lin2^T + b2 ----------------
__global__ void readout_kernel(const float* __restrict__ lin1_w, const float* __restrict__ lin1_b,
                               const float* __restrict__ lin2_w, const float* __restrict__ lin2_b,
                               float* __restrict__ y)
{
    int b = blockIdx.x, t = threadIdx.x;   // 64 threads
    __shared__ float q[128];
    __shared__ float red[64];
    q[t] = g_qstar[b * 128 + t];
    q[64 + t] = g_qstar[b * 128 + 64 + t];
    __syncthreads();

    float acc = lin1_b[t];
    const float* w = lin1_w + (size_t)t * 128;
#pragma unroll 8
    for (int k = 0; k < 128; k++) acc += q[k] * w[k];
    float z = fmaxf(acc, 0.f);

    red[t] = z * lin2_w[t];
    __syncthreads();
    for (int st = 32; st > 0; st >>= 1) { if (t < st) red[t] += red[t + st]; __syncthreads(); }
    if (t == 0) y[b] = red[0] + lin2_b[0];
}

// ======================================================================================
extern "C" void kernel_launch(void* const* d_in, const int* in_sizes, int n_in,
                              void* d_out, int out_size)
{
    const float* x        = (const float*)d_in[0];
    const int*   ei       = (const int*)  d_in[1];
    const float* ea       = (const float*)d_in[2];
    const int*   batch    = (const int*)  d_in[3];
    const float* lin0_w   = (const float*)d_in[4];
    const float* lin0_b   = (const float*)d_in[5];
    const float* nn1_w    = (const float*)d_in[6];
    const float* nn1_b    = (const float*)d_in[7];
    const float* nn2_w    = (const float*)d_in[8];
    const float* nn2_b    = (const float*)d_in[9];
    const float* root_w   = (const float*)d_in[10];
    const float* conv_b   = (const float*)d_in[11];
    const float* gru_w_ih = (const float*)d_in[12];
    const float* gru_w_hh = (const float*)d_in[13];
    const float* gru_b_ih = (const float*)d_in[14];
    const float* gru_b_hh = (const float*)d_in[15];
    const float* lstm_w_ih= (const float*)d_in[16];
    const float* lstm_w_hh= (const float*)d_in[17];
    const float* lstm_b_ih= (const float*)d_in[18];
    const float* lstm_b_hh= (const float*)d_in[19];
    const float* lin1_w   = (const float*)d_in[20];
    const float* lin1_b   = (const float*)d_in[21];
    const float* lin2_w   = (const float*)d_in[22];
    const float* lin2_b   = (const float*)d_in[23];
    float* y = (float*)d_out;

    const int N = NNODES, E = NEDGES;

    float *We, *hedge, *h, *agg, *m, *gi, *gh, *invdeg, *qstar, *hs, *cs;
    int *degi, *cnt;
    cudaGetSymbolAddress((void**)&We, g_We);
    cudaGetSymbolAddress((void**)&hedge, g_hedge);
    cudaGetSymbolAddress((void**)&h, g_h);
    cudaGetSymbolAddress((void**)&agg, g_agg);
    cudaGetSymbolAddress((void**)&m, g_m);
    cudaGetSymbolAddress((void**)&gi, g_gi);
    cudaGetSymbolAddress((void**)&gh, g_gh);
    cudaGetSymbolAddress((void**)&invdeg, g_invdeg);
    cudaGetSymbolAddress((void**)&qstar, g_qstar);
    cudaGetSymbolAddress((void**)&hs, g_hs);
    cudaGetSymbolAddress((void**)&cs, g_cs);
    cudaGetSymbolAddress((void**)&degi, g_degi);
    cudaGetSymbolAddress((void**)&cnt, g_cnt);

    // ---- bookkeeping: degrees + sorted-batch segment starts ----
    cudaMemsetAsync(degi, 0, N * sizeof(int));
    cudaMemsetAsync(cnt, 0, NG * sizeof(int));
    count_deg_kernel<<<(E + 255) / 256, 256>>>(ei, E);
    count_batch_kernel<<<(N + 255) / 256, 256>>>(batch, N);
    invdeg_kernel<<<(N + 255) / 256, 256>>>(N);
    scan_kernel<<<1, NG>>>();

    // ---- edge MLP: h_edge = relu(ea @ nn1^T + b);  We = h_edge @ nn2^T + b ----
    {
        dim3 g1(EHID / BN, (E + BM - 1) / BM);
        gemm_kernel<<<g1, 256>>>(ea, nn1_w, nn1_b, nullptr, nullptr, hedge, E, EHID, 5, 1);
        dim3 g2(WE_COLS / BN, (E + BM - 1) / BM);
        gemm_kernel<<<g2, 256>>>(hedge, nn2_w, nn2_b, nullptr, nullptr, We, E, WE_COLS, EHID, 0);
    }

    // ---- lin0: h = out = relu(x @ lin0^T + b) ----
    {
        dim3 g(DIMV / BN, (N + BM - 1) / BM);
        gemm_kernel<<<g, 256>>>(x, lin0_w, lin0_b, nullptr, nullptr, h, N, DIMV, NFEAT, 1);
    }

    // ---- 3x NNConv + GRU ----
    for (int it = 0; it < 3; it++) {
        cudaMemsetAsync(agg, 0, (size_t)N * DIMV * sizeof(float));
        msg_kernel<<<(E + 3) / 4, 256>>>(ei, E);
        dim3 gm_(DIMV / BN, (N + BM - 1) / BM);
        gemm_kernel<<<gm_, 256>>>(h, root_w, conv_b, agg, invdeg, m, N, DIMV, DIMV, 1);
        dim3 gg(3 * DIMV / BN, (N + BM - 1) / BM);
        gemm_kernel<<<gg, 256>>>(m, gru_w_ih, gru_b_ih, nullptr, nullptr, gi, N, 3 * DIMV, DIMV, 0);
        gemm_kernel<<<gg, 256>>>(h, gru_w_hh, gru_b_hh, nullptr, nullptr, gh, N, 3 * DIMV, DIMV, 0);
        gru_kernel<<<(N * DIMV + 255) / 256, 256>>>(N);
    }

    // ---- Set2Set ----
    cudaMemsetAsync(qstar, 0, NG * 2 * DIMV * sizeof(float));
    cudaMemsetAsync(hs, 0, NG * DIMV * sizeof(float));
    cudaMemsetAsync(cs, 0, NG * DIMV * sizeof(float));
    for (int s = 0; s < 3; s++) {
        lstm_kernel<<<NG, 256>>>(lstm_w_ih, lstm_w_hh, lstm_b_ih, lstm_b_hh);
        attn_kernel<<<NG, 64>>>();
    }

    // ---- readout ----
    readout_kernel<<<NG, 64>>>(lin1_w, lin1_b, lin2_w, lin2_b, y);
}

// round 2
// speedup vs baseline: 3.3974x; 3.3974x over previous
#include <cuda_runtime.h>
#include <cuda_fp16.h>
#include <math.h>
#include <stdint.h>

#define DIMV   64
#define NG     512
#define NNODES 20000
#define NEDGES 60000
#define NFEAT  11
#define EHID   128
#define WE_COLS 4096   // DIM*DIM

// ---------------- scratch (__device__ globals; no allocations allowed) ----------------
__device__ __half g_We_h[(size_t)NEDGES * WE_COLS];   // 491 MB (fp16)
__device__ __half g_hedge_h[NEDGES * EHID];           // 15.4 MB (fp16)
__device__ __half g_nn2w_h[WE_COLS * EHID];           // 1 MB (fp16)
__device__ float g_h[NNODES * DIMV];                  // node state (out == h)
__device__ float g_agg[NNODES * DIMV];
__device__ float g_m[NNODES * DIMV];
__device__ float g_gi[NNODES * 3 * DIMV];
__device__ float g_gh[NNODES * 3 * DIMV];
__device__ float g_invdeg[NNODES];
__device__ int   g_degi[NNODES];
__device__ int   g_cnt[NG];
__device__ int   g_gstart[NG + 1];
__device__ float g_ebuf[NNODES];
__device__ float g_qstar[NG * 2 * DIMV];
__device__ float g_hs[NG * DIMV];
__device__ float g_cs[NG * DIMV];

// ---------------- generic fp32 GEMM (small node GEMMs):  C = act(A@W^T + bias + addend*rowscale)
#define BM 64
#define BN 64
#define BKK 16

__global__ void gemm_kernel(const float* __restrict__ A, const float* __restrict__ W,
                            const float* __restrict__ bias,
                            const float* __restrict__ addend, const float* __restrict__ rowscale,
                            float* __restrict__ C, int M, int Nc, int K, int do_relu)
{
    __shared__ float As[BKK][BM];
    __shared__ float Ws[BKK][BN];

    const int bm = blockIdx.y * BM;
    const int bn = blockIdx.x * BN;
    const int tid = threadIdx.x;           // 256 threads
    const int tm = (tid / 16) * 4;
    const int tn = (tid % 16) * 4;

    float acc[4][4];
#pragma unroll
    for (int i = 0; i < 4; i++)
#pragma unroll
        for (int j = 0; j < 4; j++) acc[i][j] = 0.f;

    for (int k0 = 0; k0 < K; k0 += BKK) {
#pragma unroll
        for (int r = 0; r < 4; r++) {
            int idx = tid + r * 256;
            int mm = idx / BKK, kk = idx % BKK;
            int gm = bm + mm, gk = k0 + kk;
            float v = 0.f;
            if (gm < M && gk < K) v = A[(size_t)gm * K + gk];
            As[kk][mm] = v;
        }
#pragma unroll
        for (int r = 0; r < 4; r++) {
            int idx = tid + r * 256;
            int nn = idx / BKK, kk = idx % BKK;
            int gn = bn + nn, gk = k0 + kk;
            float v = 0.f;
            if (gn < Nc && gk < K) v = W[(size_t)gn * K + gk];
            Ws[kk][nn] = v;
        }
        __syncthreads();

#pragma unroll
        for (int kk = 0; kk < BKK; kk++) {
            float a0 = As[kk][tm + 0], a1 = As[kk][tm + 1], a2 = As[kk][tm + 2], a3 = As[kk][tm + 3];
            float b0 = Ws[kk][tn + 0], b1 = Ws[kk][tn + 1], b2 = Ws[kk][tn + 2], b3 = Ws[kk][tn + 3];
            acc[0][0] += a0 * b0; acc[0][1] += a0 * b1; acc[0][2] += a0 * b2; acc[0][3] += a0 * b3;
            acc[1][0] += a1 * b0; acc[1][1] += a1 * b1; acc[1][2] += a1 * b2; acc[1][3] += a1 * b3;
            acc[2][0] += a2 * b0; acc[2][1] += a2 * b1; acc[2][2] += a2 * b2; acc[2][3] += a2 * b3;
            acc[3][0] += a3 * b0; acc[3][1] += a3 * b1; acc[3][2] += a3 * b2; acc[3][3] += a3 * b3;
        }
        __syncthreads();
    }

#pragma unroll
    for (int i = 0; i < 4; i++) {
        int gm = bm + tm + i;
        if (gm >= M) continue;
        float rs = rowscale ? rowscale[gm] : 1.f;
#pragma unroll
        for (int j = 0; j < 4; j++) {
            int gn = bn + tn + j;
            if (gn >= Nc) continue;
            float v = acc[i][j];
            if (bias)   v += bias[gn];
            if (addend) v += addend[(size_t)gm * Nc + gn] * rs;
            if (do_relu) v = fmaxf(v, 0.f);
            C[(size_t)gm * Nc + gn] = v;
        }
    }
}

// ---------------- fp16 weight conversion ----------------
__global__ void f2h_kernel(const float* __restrict__ src, __half* __restrict__ dst, int n)
{
    int i = blockIdx.x * blockDim.x + threadIdx.x;
    if (i < n) dst[i] = __float2half(src[i]);
}

// ---------------- edge MLP layer 1: hedge = relu(ea @ nn1^T + b)  -> fp16 ----------------
__global__ void edge_mlp1_kernel(const float* __restrict__ ea,
                                 const float* __restrict__ nn1_w, const float* __restrict__ nn1_b,
                                 int E)
{
    int idx = blockIdx.x * blockDim.x + threadIdx.x;
    if (idx >= E * EHID) return;
    int e = idx / EHID, j = idx % EHID;
    float acc = nn1_b[j];
    const float* w = nn1_w + j * 5;
    const float* a = ea + e * 5;
#pragma unroll
    for (int k = 0; k < 5; k++) acc += a[k] * __ldg(&w[k]);
    g_hedge_h[idx] = __float2half(fmaxf(acc, 0.f));
}

// ---------------- big GEMM on tensor cores: We = hedge[E,128] @ nn2_w^T[128,4096] + b ----------
#define GBM 128
#define GBN 64
#define GBK 64

__device__ __forceinline__ void mma16816(float c[4], const uint32_t a[4], uint32_t b0, uint32_t b1)
{
    asm volatile(
        "mma.sync.aligned.m16n8k16.row.col.f32.f16.f16.f32 "
        "{%0,%1,%2,%3}, {%4,%5,%6,%7}, {%8,%9}, {%0,%1,%2,%3};\n"
        : "+f"(c[0]), "+f"(c[1]), "+f"(c[2]), "+f"(c[3])
        : "r"(a[0]), "r"(a[1]), "r"(a[2]), "r"(a[3]), "r"(b0), "r"(b1));
}

__global__ void we_gemm_kernel(const __half* __restrict__ A,   // [M,128] hedge fp16
                               const __half* __restrict__ B,   // [4096,128] nn2_w fp16
                               const float* __restrict__ bias, // nn2_b fp32
                               __half* __restrict__ C, int M)
{
    __shared__ __half As[GBM][GBK + 8];
    __shared__ __half Bs[GBN][GBK + 8];

    const int bm = blockIdx.y * GBM;
    const int bn = blockIdx.x * GBN;
    const int tid = threadIdx.x;              // 256
    const int warp = tid >> 5, lane = tid & 31;
    const int wm = (warp & 3) * 32;           // 4 warps along M
    const int wn = (warp >> 2) * 32;          // 2 warps along N

    float c[2][4][4];
#pragma unroll
    for (int mt = 0; mt < 2; mt++)
#pragma unroll
        for (int nt = 0; nt < 4; nt++)
#pragma unroll
            for (int i = 0; i < 4; i++) c[mt][nt][i] = 0.f;

    for (int ks = 0; ks < EHID; ks += GBK) {
        // A tile: 128 rows x 64 halves = 1024 uint4
#pragma unroll
        for (int r = 0; r < 4; r++) {
            int idx = tid + r * 256;
            int row = idx >> 3, u = idx & 7;
            int gm = bm + row;
            uint4 v = make_uint4(0u, 0u, 0u, 0u);
            if (gm < M) v = *(const uint4*)(A + (size_t)gm * EHID + ks + u * 8);
            *(uint4*)(&As[row][u * 8]) = v;
        }
        // B tile: 64 rows x 64 halves = 512 uint4
#pragma unroll
        for (int r = 0; r < 2; r++) {
            int idx = tid + r * 256;
            int row = idx >> 3, u = idx & 7;
            uint4 v = *(const uint4*)(B + (size_t)(bn + row) * EHID + ks + u * 8);
            *(uint4*)(&Bs[row][u * 8]) = v;
        }
        __syncthreads();

#pragma unroll
        for (int k0 = 0; k0 < GBK; k0 += 16) {
            uint32_t af[2][4];
            const int col = k0 + 2 * (lane & 3);
#pragma unroll
            for (int mt = 0; mt < 2; mt++) {
                int row = wm + mt * 16 + (lane >> 2);
                af[mt][0] = *(const uint32_t*)&As[row][col];
                af[mt][1] = *(const uint32_t*)&As[row + 8][col];
                af[mt][2] = *(const uint32_t*)&As[row][col + 8];
                af[mt][3] = *(const uint32_t*)&As[row + 8][col + 8];
            }
#pragma unroll
            for (int nt = 0; nt < 4; nt++) {
                int n = wn + nt * 8 + (lane >> 2);
                uint32_t b0 = *(const uint32_t*)&Bs[n][col];
                uint32_t b1 = *(const uint32_t*)&Bs[n][col + 8];
                mma16816(c[0][nt], af[0], b0, b1);
                mma16816(c[1][nt], af[1], b0, b1);
            }
        }
        __syncthreads();
    }

    // epilogue: + bias, convert to fp16
#pragma unroll
    for (int mt = 0; mt < 2; mt++) {
        int row0 = bm + wm + mt * 16 + (lane >> 2);
#pragma unroll
        for (int nt = 0; nt < 4; nt++) {
            int gn = bn + wn + nt * 8 + 2 * (lane & 3);
            float b0 = bias[gn], b1 = bias[gn + 1];
            if (row0 < M) {
                __half2 h = __floats2half2_rn(c[mt][nt][0] + b0, c[mt][nt][1] + b1);
                *(__half2*)(C + (size_t)row0 * WE_COLS + gn) = h;
            }
            if (row0 + 8 < M) {
                __half2 h = __floats2half2_rn(c[mt][nt][2] + b0, c[mt][nt][3] + b1);
                *(__half2*)(C + (size_t)(row0 + 8) * WE_COLS + gn) = h;
            }
        }
    }
}

// ---------------- degree / batch bookkeeping ----------------
__global__ void count_deg_kernel(const int* __restrict__ ei, int E)
{
    int e = blockIdx.x * blockDim.x + threadIdx.x;
    if (e < E) atomicAdd(&g_degi[ei[E + e]], 1);
}

__global__ void count_batch_kernel(const int* __restrict__ batch, int N)
{
    int i = blockIdx.x * blockDim.x + threadIdx.x;
    if (i < N) atomicAdd(&g_cnt[batch[i]], 1);
}

__global__ void invdeg_kernel(int N)
{
    int i = blockIdx.x * blockDim.x + threadIdx.x;
    if (i < N) g_invdeg[i] = 1.f / fmaxf((float)g_degi[i], 1.f);
}

__global__ void scan_kernel()
{
    __shared__ int s[NG];
    int t = threadIdx.x;
    s[t] = g_cnt[t];
    __syncthreads();
    for (int off = 1; off < NG; off <<= 1) {
        int v = (t >= off) ? s[t - off] : 0;
        __syncthreads();
        s[t] += v;
        __syncthreads();
    }
    if (t == 0) g_gstart[0] = 0;
    g_gstart[t + 1] = s[t];
}

// ---------------- per-edge message + scatter: agg[dst] += out[src] @ We[e]  (fp16 We) ----------
__global__ void msg_kernel(const int* __restrict__ ei, int E)
{
    const int w    = threadIdx.x >> 5;     // 8 edges per 256-thread block (1 warp/edge)
    const int lane = threadIdx.x & 31;
    const int e    = blockIdx.x * 8 + w;
    __shared__ float s_a[8][DIMV];

    if (e >= E) return;
    int src = ei[e];
    int dst = ei[E + e];
    s_a[w][lane]      = g_h[src * DIMV + lane];
    s_a[w][lane + 32] = g_h[src * DIMV + lane + 32];
    __syncwarp();

    const __half2* __restrict__ wp = (const __half2*)(g_We_h + (size_t)e * WE_COLS) + lane;
    float accx = 0.f, accy = 0.f;
#pragma unroll
    for (int i = 0; i < DIMV; i++) {
        float a = s_a[w][i];
        float2 wv = __half22float2(wp[i * 32]);
        accx = fmaf(a, wv.x, accx);
        accy = fmaf(a, wv.y, accy);
    }
    atomicAdd(&g_agg[dst * DIMV + 2 * lane],     accx);
    atomicAdd(&g_agg[dst * DIMV + 2 * lane + 1], accy);
}

// ---------------- GRU elementwise update (PyTorch r,z,n layout) ----------------
__global__ void gru_kernel(int N)
{
    int idx = blockIdx.x * blockDim.x + threadIdx.x;
    if (idx >= N * DIMV) return;
    int n = idx / DIMV, d = idx % DIMV;
    const float* gi = g_gi + (size_t)n * 3 * DIMV;
    const float* gh = g_gh + (size_t)n * 3 * DIMV;
    float ir = gi[d], iz = gi[DIMV + d], in_ = gi[2 * DIMV + d];
    float hr = gh[d], hz = gh[DIMV + d], hn  = gh[2 * DIMV + d];
    float r = 1.f / (1.f + expf(-(ir + hr)));
    float z = 1.f / (1.f + expf(-(iz + hz)));
    float nn = tanhf(in_ + r * hn);
    float h = g_h[idx];
    g_h[idx] = (1.f - z) * nn + z * h;
}

// ---------------- Set2Set LSTM step ----------------
__global__ void lstm_kernel(const float* __restrict__ w_ih, const float* __restrict__ w_hh,
                            const float* __restrict__ b_ih, const float* __restrict__ b_hh)
{
    int b = blockIdx.x, t = threadIdx.x;
    __shared__ float qs[2 * DIMV];
    __shared__ float hsh[DIMV];
    __shared__ float gates[4 * DIMV];
    if (t < 128) qs[t] = g_qstar[b * 128 + t];
    if (t < 64)  hsh[t] = g_hs[b * 64 + t];
    __syncthreads();

    float acc = b_ih[t] + b_hh[t];
    const float* wih = w_ih + (size_t)t * 128;
    const float* whh = w_hh + (size_t)t * 64;
#pragma unroll 8
    for (int k = 0; k < 128; k++) acc += qs[k] * wih[k];
#pragma unroll 8
    for (int k = 0; k < 64; k++)  acc += hsh[k] * whh[k];
    gates[t] = acc;
    __syncthreads();

    if (t < 64) {
        float i = 1.f / (1.f + expf(-gates[t]));
        float f = 1.f / (1.f + expf(-gates[64 + t]));
        float g = tanhf(gates[128 + t]);
        float o = 1.f / (1.f + expf(-gates[192 + t]));
        float c = f * g_cs[b * 64 + t] + i * g;
        g_cs[b * 64 + t] = c;
        g_hs[b * 64 + t] = o * tanhf(c);
    }
}

// ---------------- Set2Set attention (one block = one graph; batch is sorted) ------------------
__global__ void attn_kernel()
{
    int b = blockIdx.x, t = threadIdx.x;   // 64 threads
    int s = g_gstart[b], e_end = g_gstart[b + 1];
    __shared__ float q[DIMV];
    __shared__ float red[DIMV];
    q[t] = g_hs[b * DIMV + t];
    __syncthreads();

    float lmax = -1e30f;
    for (int n = s + t; n < e_end; n += 64) {
        const float* row = g_h + (size_t)n * DIMV;
        float acc = 0.f;
#pragma unroll 8
        for (int i = 0; i < DIMV; i++) acc += row[i] * q[i];
        g_ebuf[n] = acc;
        lmax = fmaxf(lmax, acc);
    }
    red[t] = lmax; __syncthreads();
    for (int st = 32; st > 0; st >>= 1) { if (t < st) red[t] = fmaxf(red[t], red[t + st]); __syncthreads(); }
    float gmax = red[0];
    __syncthreads();

    float lsum = 0.f;
    for (int n = s + t; n < e_end; n += 64) {
        float a = expf(g_ebuf[n] - gmax);
        g_ebuf[n] = a;
        lsum += a;
    }
    red[t] = lsum; __syncthreads();
    for (int st = 32; st > 0; st >>= 1) { if (t < st) red[t] += red[t + st]; __syncthreads(); }
    float S = red[0];
    __syncthreads();

    float r = 0.f;
    for (int n = s; n < e_end; n++) r += g_ebuf[n] * g_h[(size_t)n * DIMV + t];

    g_qstar[b * 128 + t] = q[t];
    g_qstar[b * 128 + 64 + t] = (e_end > s) ? (r / S) : 0.f;
}

// ---------------- readout ----------------
__global__ void readout_kernel(const float* __restrict__ lin1_w, const float* __restrict__ lin1_b,
                               const float* __restrict__ lin2_w, const float* __restrict__ lin2_b,
                               float* __restrict__ y)
{
    int b = blockIdx.x, t = threadIdx.x;   // 64 threads
    __shared__ float q[128];
    __shared__ float red[64];
    q[t] = g_qstar[b * 128 + t];
    q[64 + t] = g_qstar[b * 128 + 64 + t];
    __syncthreads();

    float acc = lin1_b[t];
    const float* w = lin1_w + (size_t)t * 128;
#pragma unroll 8
    for (int k = 0; k < 128; k++) acc += q[k] * w[k];
    float z = fmaxf(acc, 0.f);

    red[t] = z * lin2_w[t];
    __syncthreads();
    for (int st = 32; st > 0; st >>= 1) { if (t < st) red[t] += red[t + st]; __syncthreads(); }
    if (t == 0) y[b] = red[0] + lin2_b[0];
}

// ======================================================================================
extern "C" void kernel_launch(void* const* d_in, const int* in_sizes, int n_in,
                              void* d_out, int out_size)
{
    const float* x        = (const float*)d_in[0];
    const int*   ei       = (const int*)  d_in[1];
    const float* ea       = (const float*)d_in[2];
    const int*   batch    = (const int*)  d_in[3];
    const float* lin0_w   = (const float*)d_in[4];
    const float* lin0_b   = (const float*)d_in[5];
    const float* nn1_w    = (const float*)d_in[6];
    const float* nn1_b    = (const float*)d_in[7];
    const float* nn2_w    = (const float*)d_in[8];
    const float* nn2_b    = (const float*)d_in[9];
    const float* root_w   = (const float*)d_in[10];
    const float* conv_b   = (const float*)d_in[11];
    const float* gru_w_ih = (const float*)d_in[12];
    const float* gru_w_hh = (const float*)d_in[13];
    const float* gru_b_ih = (const float*)d_in[14];
    const float* gru_b_hh = (const float*)d_in[15];
    const float* lstm_w_ih= (const float*)d_in[16];
    const float* lstm_w_hh= (const float*)d_in[17];
    const float* lstm_b_ih= (const float*)d_in[18];
    const float* lstm_b_hh= (const float*)d_in[19];
    const float* lin1_w   = (const float*)d_in[20];
    const float* lin1_b   = (const float*)d_in[21];
    const float* lin2_w   = (const float*)d_in[22];
    const float* lin2_b   = (const float*)d_in[23];
    float* y = (float*)d_out;

    const int N = NNODES, E = NEDGES;

    __half *We_h, *hedge_h, *nn2w_h;
    float *h, *agg, *m, *gi, *gh, *invdeg, *qstar, *hs, *cs;
    int *degi, *cnt;
    cudaGetSymbolAddress((void**)&We_h, g_We_h);
    cudaGetSymbolAddress((void**)&hedge_h, g_hedge_h);
    cudaGetSymbolAddress((void**)&nn2w_h, g_nn2w_h);
    cudaGetSymbolAddress((void**)&h, g_h);
    cudaGetSymbolAddress((void**)&agg, g_agg);
    cudaGetSymbolAddress((void**)&m, g_m);
    cudaGetSymbolAddress((void**)&gi, g_gi);
    cudaGetSymbolAddress((void**)&gh, g_gh);
    cudaGetSymbolAddress((void**)&invdeg, g_invdeg);
    cudaGetSymbolAddress((void**)&qstar, g_qstar);
    cudaGetSymbolAddress((void**)&hs, g_hs);
    cudaGetSymbolAddress((void**)&cs, g_cs);
    cudaGetSymbolAddress((void**)&degi, g_degi);
    cudaGetSymbolAddress((void**)&cnt, g_cnt);

    // ---- bookkeeping: degrees + sorted-batch segment starts ----
    cudaMemsetAsync(degi, 0, N * sizeof(int));
    cudaMemsetAsync(cnt, 0, NG * sizeof(int));
    count_deg_kernel<<<(E + 255) / 256, 256>>>(ei, E);
    count_batch_kernel<<<(N + 255) / 256, 256>>>(batch, N);
    invdeg_kernel<<<(N + 255) / 256, 256>>>(N);
    scan_kernel<<<1, NG>>>();

    // ---- weight conversion + edge MLP ----
    f2h_kernel<<<(WE_COLS * EHID + 255) / 256, 256>>>(nn2_w, nn2w_h, WE_COLS * EHID);
    edge_mlp1_kernel<<<(E * EHID + 255) / 256, 256>>>(ea, nn1_w, nn1_b, E);

    // ---- big GEMM on tensor cores: We (fp16) ----
    {
        dim3 g(WE_COLS / GBN, (E + GBM - 1) / GBM);
        we_gemm_kernel<<<g, 256>>>(hedge_h, nn2w_h, nn2_b, We_h, E);
    }

    // ---- lin0: h = relu(x @ lin0^T + b) ----
    {
        dim3 g(DIMV / BN, (N + BM - 1) / BM);
        gemm_kernel<<<g, 256>>>(x, lin0_w, lin0_b, nullptr, nullptr, h, N, DIMV, NFEAT, 1);
    }

    // ---- 3x NNConv + GRU ----
    for (int it = 0; it < 3; it++) {
        cudaMemsetAsync(agg, 0, (size_t)N * DIMV * sizeof(float));
        msg_kernel<<<(E + 7) / 8, 256>>>(ei, E);
        dim3 gm_(DIMV / BN, (N + BM - 1) / BM);
        gemm_kernel<<<gm_, 256>>>(h, root_w, conv_b, agg, invdeg, m, N, DIMV, DIMV, 1);
        dim3 gg(3 * DIMV / BN, (N + BM - 1) / BM);
        gemm_kernel<<<gg, 256>>>(m, gru_w_ih, gru_b_ih, nullptr, nullptr, gi, N, 3 * DIMV, DIMV, 0);
        gemm_kernel<<<gg, 256>>>(h, gru_w_hh, gru_b_hh, nullptr, nullptr, gh, N, 3 * DIMV, DIMV, 0);
        gru_kernel<<<(N * DIMV + 255) / 256, 256>>>(N);
    }

    // ---- Set2Set ----
    cudaMemsetAsync(qstar, 0, NG * 2 * DIMV * sizeof(float));
    cudaMemsetAsync(hs, 0, NG * DIMV * sizeof(float));
    cudaMemsetAsync(cs, 0, NG * DIMV * sizeof(float));
    for (int s = 0; s < 3; s++) {
        lstm_kernel<<<NG, 256>>>(lstm_w_ih, lstm_w_hh, lstm_b_ih, lstm_b_hh);
        attn_kernel<<<NG, 64>>>();
    }

    // ---- readout ----
    readout_kernel<<<NG, 64>>>(lin1_w, lin1_b, lin2_w, lin2_b, y);
}

// round 3
// speedup vs baseline: 4.6728x; 1.3754x over previous
#include <cuda_runtime.h>
#include <cuda_fp16.h>
#include <math.h>
#include <stdint.h>

#define DIMV   64
#define NG     512
#define NNODES 20000
#define NEDGES 60000
#define NFEAT  11
#define EHID   128
#define WE_COLS 4096   // DIM*DIM

// ---------------- scratch (__device__ globals; no allocations allowed) ----------------
__device__ __half g_We_h[(size_t)NEDGES * WE_COLS];   // 491 MB (fp16)
__device__ __half g_hedge_h[NEDGES * EHID];           // 15.4 MB (fp16)
__device__ __half g_nn2w_h[WE_COLS * EHID];           // 1 MB (fp16)
__device__ float g_h[NNODES * DIMV];                  // node state (out == h)
__device__ float g_agg[NNODES * DIMV];
__device__ float g_m[NNODES * DIMV];
__device__ float g_gi[NNODES * 3 * DIMV];
__device__ float g_gh[NNODES * 3 * DIMV];
__device__ float g_invdeg[NNODES];
__device__ int   g_degi[NNODES];
__device__ int   g_cnt[NG];
__device__ int   g_gstart[NG + 1];
__device__ float g_ebuf[NNODES];
__device__ float g_qstar[NG * 2 * DIMV];
__device__ float g_hs[NG * DIMV];
__device__ float g_cs[NG * DIMV];
// transposed small weights (coalesced GEMV reads)
__device__ float g_wihT[128 * 256];   // lstm_w_ih^T  [2*DIM][4*DIM]
__device__ float g_whhT[64 * 256];    // lstm_w_hh^T  [DIM][4*DIM]
__device__ float g_lin1T[128 * 64];   // lin1_w^T     [2*DIM][DIM]

// ---------------- generic fp32 GEMM (small node GEMMs) ----------------
#define BM 64
#define BN 64
#define BKK 16

__global__ void gemm_kernel(const float* __restrict__ A, const float* __restrict__ W,
                            const float* __restrict__ bias,
                            const float* __restrict__ addend, const float* __restrict__ rowscale,
                            float* __restrict__ C, int M, int Nc, int K, int do_relu)
{
    __shared__ float As[BKK][BM];
    __shared__ float Ws[BKK][BN];

    const int bm = blockIdx.y * BM;
    const int bn = blockIdx.x * BN;
    const int tid = threadIdx.x;           // 256 threads
    const int tm = (tid / 16) * 4;
    const int tn = (tid % 16) * 4;

    float acc[4][4];
#pragma unroll
    for (int i = 0; i < 4; i++)
#pragma unroll
        for (int j = 0; j < 4; j++) acc[i][j] = 0.f;

    for (int k0 = 0; k0 < K; k0 += BKK) {
#pragma unroll
        for (int r = 0; r < 4; r++) {
            int idx = tid + r * 256;
            int mm = idx / BKK, kk = idx % BKK;
            int gm = bm + mm, gk = k0 + kk;
            float v = 0.f;
            if (gm < M && gk < K) v = A[(size_t)gm * K + gk];
            As[kk][mm] = v;
        }
#pragma unroll
        for (int r = 0; r < 4; r++) {
            int idx = tid + r * 256;
            int nn = idx / BKK, kk = idx % BKK;
            int gn = bn + nn, gk = k0 + kk;
            float v = 0.f;
            if (gn < Nc && gk < K) v = W[(size_t)gn * K + gk];
            Ws[kk][nn] = v;
        }
        __syncthreads();

#pragma unroll
        for (int kk = 0; kk < BKK; kk++) {
            float a0 = As[kk][tm + 0], a1 = As[kk][tm + 1], a2 = As[kk][tm + 2], a3 = As[kk][tm + 3];
            float b0 = Ws[kk][tn + 0], b1 = Ws[kk][tn + 1], b2 = Ws[kk][tn + 2], b3 = Ws[kk][tn + 3];
            acc[0][0] += a0 * b0; acc[0][1] += a0 * b1; acc[0][2] += a0 * b2; acc[0][3] += a0 * b3;
            acc[1][0] += a1 * b0; acc[1][1] += a1 * b1; acc[1][2] += a1 * b2; acc[1][3] += a1 * b3;
            acc[2][0] += a2 * b0; acc[2][1] += a2 * b1; acc[2][2] += a2 * b2; acc[2][3] += a2 * b3;
            acc[3][0] += a3 * b0; acc[3][1] += a3 * b1; acc[3][2] += a3 * b2; acc[3][3] += a3 * b3;
        }
        __syncthreads();
    }

#pragma unroll
    for (int i = 0; i < 4; i++) {
        int gm = bm + tm + i;
        if (gm >= M) continue;
        float rs = rowscale ? rowscale[gm] : 1.f;
#pragma unroll
        for (int j = 0; j < 4; j++) {
            int gn = bn + tn + j;
            if (gn >= Nc) continue;
            float v = acc[i][j];
            if (bias)   v += bias[gn];
            if (addend) v += addend[(size_t)gm * Nc + gn] * rs;
            if (do_relu) v = fmaxf(v, 0.f);
            C[(size_t)gm * Nc + gn] = v;
        }
    }
}

// ---------------- fp16 weight conversion ----------------
__global__ void f2h_kernel(const float* __restrict__ src, __half* __restrict__ dst, int n)
{
    int i = blockIdx.x * blockDim.x + threadIdx.x;
    if (i < n) dst[i] = __float2half(src[i]);
}

// ---------------- transpose small weights ----------------
__global__ void transpose_w_kernel(const float* __restrict__ w_ih, const float* __restrict__ w_hh,
                                   const float* __restrict__ lin1_w)
{
    int i = blockIdx.x * blockDim.x + threadIdx.x;
    if (i < 256 * 128) { int r = i / 128, k = i % 128; g_wihT[k * 256 + r] = w_ih[i]; }
    if (i < 256 * 64)  { int r = i / 64,  k = i % 64;  g_whhT[k * 256 + r] = w_hh[i]; }
    if (i < 64 * 128)  { int r = i / 128, k = i % 128; g_lin1T[k * 64 + r] = lin1_w[i]; }
}

// ---------------- edge MLP layer 1: hedge = relu(ea @ nn1^T + b)  -> fp16 ----------------
__global__ void edge_mlp1_kernel(const float* __restrict__ ea,
                                 const float* __restrict__ nn1_w, const float* __restrict__ nn1_b,
                                 int E)
{
    int idx = blockIdx.x * blockDim.x + threadIdx.x;
    if (idx >= E * EHID) return;
    int e = idx / EHID, j = idx % EHID;
    float acc = nn1_b[j];
    const float* w = nn1_w + j * 5;
    const float* a = ea + e * 5;
#pragma unroll
    for (int k = 0; k < 5; k++) acc += a[k] * __ldg(&w[k]);
    g_hedge_h[idx] = __float2half(fmaxf(acc, 0.f));
}

// ---------------- big GEMM on tensor cores: We = hedge[E,128] @ nn2_w^T[128,4096] + b ----------
// 128x128 tile, full K=128 single smem stage, cp.async loads, ldmatrix fragments.
#define WG_PAD 8
#define WG_LDK (EHID + WG_PAD)   // 136 halves per smem row

__device__ __forceinline__ void mma16816(float c[4], const uint32_t a[4], uint32_t b0, uint32_t b1)
{
    asm volatile(
        "mma.sync.aligned.m16n8k16.row.col.f32.f16.f16.f32 "
        "{%0,%1,%2,%3}, {%4,%5,%6,%7}, {%8,%9}, {%0,%1,%2,%3};\n"
        : "+f"(c[0]), "+f"(c[1]), "+f"(c[2]), "+f"(c[3])
        : "r"(a[0]), "r"(a[1]), "r"(a[2]), "r"(a[3]), "r"(b0), "r"(b1));
}

__global__ void __launch_bounds__(256) we_gemm_kernel(
    const __half* __restrict__ A,   // [M,128] hedge fp16
    const __half* __restrict__ B,   // [4096,128] nn2_w fp16
    const float* __restrict__ bias, // nn2_b fp32
    __half* __restrict__ C, int M)
{
    extern __shared__ __half smemh[];
    __half (*As)[WG_LDK] = (__half (*)[WG_LDK])smemh;
    __half (*Bs)[WG_LDK] = (__half (*)[WG_LDK])(smemh + 128 * WG_LDK);

    const int bm = blockIdx.y * 128;
    const int bn = blockIdx.x * 128;
    const int tid = threadIdx.x;
    const int warp = tid >> 5, lane = tid & 31;
    const int wm = (warp & 1) * 64;     // 2 warps along M (64 rows each)
    const int wn = (warp >> 1) * 32;    // 4 warps along N (32 cols each)

    // --- async loads: A and B tiles, 2048 x 16B chunks each (8 per thread each) ---
#pragma unroll
    for (int i = 0; i < 8; i++) {
        int idx = tid + i * 256;          // 0..2047
        int row = idx >> 4, u = idx & 15; // 16 chunks per 256B row
        int gm = bm + row;
        uint32_t dst = (uint32_t)__cvta_generic_to_shared(&As[row][u * 8]);
        const void* src = A + (size_t)gm * EHID + u * 8;
        int sz = (gm < M) ? 16 : 0;       // zero-fill OOB rows
        asm volatile("cp.async.ca.shared.global [%0], [%1], 16, %2;\n"
                     :: "r"(dst), "l"(src), "r"(sz));
    }
#pragma unroll
    for (int i = 0; i < 8; i++) {
        int idx = tid + i * 256;
        int row = idx >> 4, u = idx & 15;
        uint32_t dst = (uint32_t)__cvta_generic_to_shared(&Bs[row][u * 8]);
        const void* src = B + (size_t)(bn + row) * EHID + u * 8;
        asm volatile("cp.async.ca.shared.global [%0], [%1], 16;\n"
                     :: "r"(dst), "l"(src));
    }
    asm volatile("cp.async.commit_group;\n" ::: "memory");
    asm volatile("cp.async.wait_group 0;\n" ::: "memory");
    __syncthreads();

    float c[4][4][4];
#pragma unroll
    for (int mt = 0; mt < 4; mt++)
#pragma unroll
        for (int nt = 0; nt < 4; nt++)
#pragma unroll
            for (int i = 0; i < 4; i++) c[mt][nt][i] = 0.f;

    const int g = lane >> 3, r = lane & 7;

#pragma unroll
    for (int k0 = 0; k0 < EHID; k0 += 16) {
        uint32_t af[4][4];
#pragma unroll
        for (int mt = 0; mt < 4; mt++) {
            uint32_t addr = (uint32_t)__cvta_generic_to_shared(
                &As[wm + mt * 16 + r + (g & 1) * 8][k0 + (g >> 1) * 8]);
            asm volatile("ldmatrix.sync.aligned.m8n8.x4.shared.b16 {%0,%1,%2,%3}, [%4];"
                         : "=r"(af[mt][0]), "=r"(af[mt][1]), "=r"(af[mt][2]), "=r"(af[mt][3])
                         : "r"(addr));
        }
        uint32_t bf[4][2];
#pragma unroll
        for (int p = 0; p < 2; p++) {
            uint32_t addr = (uint32_t)__cvta_generic_to_shared(
                &Bs[wn + p * 16 + r + (g >> 1) * 8][k0 + (g & 1) * 8]);
            uint32_t b0, b1, b2, b3;
            asm volatile("ldmatrix.sync.aligned.m8n8.x4.shared.b16 {%0,%1,%2,%3}, [%4];"
                         : "=r"(b0), "=r"(b1), "=r"(b2), "=r"(b3) : "r"(addr));
            bf[2 * p][0] = b0; bf[2 * p][1] = b1;
            bf[2 * p + 1][0] = b2; bf[2 * p + 1][1] = b3;
        }
#pragma unroll
        for (int mt = 0; mt < 4; mt++)
#pragma unroll
            for (int nt = 0; nt < 4; nt++)
                mma16816(c[mt][nt], af[mt], bf[nt][0], bf[nt][1]);
    }

    // epilogue: + bias, convert to fp16
#pragma unroll
    for (int mt = 0; mt < 4; mt++) {
        int row0 = bm + wm + mt * 16 + (lane >> 2);
#pragma unroll
        for (int nt = 0; nt < 4; nt++) {
            int gn = bn + wn + nt * 8 + 2 * (lane & 3);
            float b0 = bias[gn], b1 = bias[gn + 1];
            if (row0 < M) {
                __half2 h = __floats2half2_rn(c[mt][nt][0] + b0, c[mt][nt][1] + b1);
                *(__half2*)(C + (size_t)row0 * WE_COLS + gn) = h;
            }
            if (row0 + 8 < M) {
                __half2 h = __floats2half2_rn(c[mt][nt][2] + b0, c[mt][nt][3] + b1);
                *(__half2*)(C + (size_t)(row0 + 8) * WE_COLS + gn) = h;
            }
        }
    }
}

// ---------------- degree / batch bookkeeping ----------------
__global__ void count_deg_kernel(const int* __restrict__ ei, int E)
{
    int e = blockIdx.x * blockDim.x + threadIdx.x;
    if (e < E) atomicAdd(&g_degi[ei[E + e]], 1);
}

__global__ void count_batch_kernel(const int* __restrict__ batch, int N)
{
    int i = blockIdx.x * blockDim.x + threadIdx.x;
    if (i < N) atomicAdd(&g_cnt[batch[i]], 1);
}

__global__ void invdeg_kernel(int N)
{
    int i = blockIdx.x * blockDim.x + threadIdx.x;
    if (i < N) g_invdeg[i] = 1.f / fmaxf((float)g_degi[i], 1.f);
}

__global__ void scan_kernel()
{
    __shared__ int s[NG];
    int t = threadIdx.x;
    s[t] = g_cnt[t];
    __syncthreads();
    for (int off = 1; off < NG; off <<= 1) {
        int v = (t >= off) ? s[t - off] : 0;
        __syncthreads();
        s[t] += v;
        __syncthreads();
    }
    if (t == 0) g_gstart[0] = 0;
    g_gstart[t + 1] = s[t];
}

// ---------------- per-edge message + scatter: agg[dst] += out[src] @ We[e]  (fp16 We) ----------
__global__ void msg_kernel(const int* __restrict__ ei, int E)
{
    const int w    = threadIdx.x >> 5;     // 8 edges per 256-thread block (1 warp/edge)
    const int lane = threadIdx.x & 31;
    const int e    = blockIdx.x * 8 + w;
    __shared__ float s_a[8][DIMV];

    if (e >= E) return;
    int src = ei[e];
    int dst = ei[E + e];
    s_a[w][lane]      = g_h[src * DIMV + lane];
    s_a[w][lane + 32] = g_h[src * DIMV + lane + 32];
    __syncwarp();

    const __half2* __restrict__ wp = (const __half2*)(g_We_h + (size_t)e * WE_COLS) + lane;
    float accx = 0.f, accy = 0.f;
#pragma unroll
    for (int i = 0; i < DIMV; i++) {
        float a = s_a[w][i];
        float2 wv = __half22float2(wp[i * 32]);
        accx = fmaf(a, wv.x, accx);
        accy = fmaf(a, wv.y, accy);
    }
    atomicAdd(&g_agg[dst * DIMV + 2 * lane],     accx);
    atomicAdd(&g_agg[dst * DIMV + 2 * lane + 1], accy);
}

// ---------------- GRU elementwise update (PyTorch r,z,n layout) ----------------
__global__ void gru_kernel(int N)
{
    int idx = blockIdx.x * blockDim.x + threadIdx.x;
    if (idx >= N * DIMV) return;
    int n = idx / DIMV, d = idx % DIMV;
    const float* gi = g_gi + (size_t)n * 3 * DIMV;
    const float* gh = g_gh + (size_t)n * 3 * DIMV;
    float ir = gi[d], iz = gi[DIMV + d], in_ = gi[2 * DIMV + d];
    float hr = gh[d], hz = gh[DIMV + d], hn  = gh[2 * DIMV + d];
    float r = 1.f / (1.f + expf(-(ir + hr)));
    float z = 1.f / (1.f + expf(-(iz + hz)));
    float nn = tanhf(in_ + r * hn);
    float h = g_h[idx];
    g_h[idx] = (1.f - z) * nn + z * h;
}

// ---------------- Set2Set LSTM step (transposed weights, coalesced) ----------------
__global__ void lstm_kernel(const float* __restrict__ b_ih, const float* __restrict__ b_hh)
{
    int b = blockIdx.x, t = threadIdx.x;   // 256 threads = 256 gates
    __shared__ float qs[2 * DIMV];
    __shared__ float hsh[DIMV];
    __shared__ float gates[4 * DIMV];
    if (t < 128) qs[t] = g_qstar[b * 128 + t];
    if (t < 64)  hsh[t] = g_hs[b * 64 + t];
    __syncthreads();

    float acc = b_ih[t] + b_hh[t];
#pragma unroll 8
    for (int k = 0; k < 128; k++) acc += qs[k] * g_wihT[k * 256 + t];
#pragma unroll 8
    for (int k = 0; k < 64; k++)  acc += hsh[k] * g_whhT[k * 256 + t];
    gates[t] = acc;
    __syncthreads();

    if (t < 64) {
        float i = 1.f / (1.f + expf(-gates[t]));
        float f = 1.f / (1.f + expf(-gates[64 + t]));
        float g = tanhf(gates[128 + t]);
        float o = 1.f / (1.f + expf(-gates[192 + t]));
        float c = f * g_cs[b * 64 + t] + i * g;
        g_cs[b * 64 + t] = c;
        g_hs[b * 64 + t] = o * tanhf(c);
    }
}

// ---------------- Set2Set attention (one block = one graph; batch is sorted) ------------------
__global__ void attn_kernel()
{
    int b = blockIdx.x, t = threadIdx.x;   // 64 threads
    int s = g_gstart[b], e_end = g_gstart[b + 1];
    __shared__ float q[DIMV];
    __shared__ float red[DIMV];
    q[t] = g_hs[b * DIMV + t];
    __syncthreads();

    float lmax = -1e30f;
    for (int n = s + t; n < e_end; n += 64) {
        const float* row = g_h + (size_t)n * DIMV;
        float acc = 0.f;
#pragma unroll 8
        for (int i = 0; i < DIMV; i++) acc += row[i] * q[i];
        g_ebuf[n] = acc;
        lmax = fmaxf(lmax, acc);
    }
    red[t] = lmax; __syncthreads();
    for (int st = 32; st > 0; st >>= 1) { if (t < st) red[t] = fmaxf(red[t], red[t + st]); __syncthreads(); }
    float gmax = red[0];
    __syncthreads();

    float lsum = 0.f;
    for (int n = s + t; n < e_end; n += 64) {
        float a = expf(g_ebuf[n] - gmax);
        g_ebuf[n] = a;
        lsum += a;
    }
    red[t] = lsum; __syncthreads();
    for (int st = 32; st > 0; st >>= 1) { if (t < st) red[t] += red[t + st]; __syncthreads(); }
    float S = red[0];
    __syncthreads();

    float r = 0.f;
    for (int n = s; n < e_end; n++) r += g_ebuf[n] * g_h[(size_t)n * DIMV + t];

    g_qstar[b * 128 + t] = q[t];
    g_qstar[b * 128 + 64 + t] = (e_end > s) ? (r / S) : 0.f;
}

// ---------------- readout ----------------
__global__ void readout_kernel(const float* __restrict__ lin1_b,
                               const float* __restrict__ lin2_w, const float* __restrict__ lin2_b,
                               float* __restrict__ y)
{
    int b = blockIdx.x, t = threadIdx.x;   // 64 threads
    __shared__ float q[128];
    __shared__ float red[64];
    q[t] = g_qstar[b * 128 + t];
    q[64 + t] = g_qstar[b * 128 + 64 + t];
    __syncthreads();

    float acc = lin1_b[t];
#pragma unroll 8
    for (int k = 0; k < 128; k++) acc += q[k] * g_lin1T[k * 64 + t];
    float z = fmaxf(acc, 0.f);

    red[t] = z * lin2_w[t];
    __syncthreads();
    for (int st = 32; st > 0; st >>= 1) { if (t < st) red[t] += red[t + st]; __syncthreads(); }
    if (t == 0) y[b] = red[0] + lin2_b[0];
}

// ======================================================================================
extern "C" void kernel_launch(void* const* d_in, const int* in_sizes, int n_in,
                              void* d_out, int out_size)
{
    const float* x        = (const float*)d_in[0];
    const int*   ei       = (const int*)  d_in[1];
    const float* ea       = (const float*)d_in[2];
    const int*   batch    = (const int*)  d_in[3];
    const float* lin0_w   = (const float*)d_in[4];
    const float* lin0_b   = (const float*)d_in[5];
    const float* nn1_w    = (const float*)d_in[6];
    const float* nn1_b    = (const float*)d_in[7];
    const float* nn2_w    = (const float*)d_in[8];
    const float* nn2_b    = (const float*)d_in[9];
    const float* root_w   = (const float*)d_in[10];
    const float* conv_b   = (const float*)d_in[11];
    const float* gru_w_ih = (const float*)d_in[12];
    const float* gru_w_hh = (const float*)d_in[13];
    const float* gru_b_ih = (const float*)d_in[14];
    const float* gru_b_hh = (const float*)d_in[15];
    const float* lstm_w_ih= (const float*)d_in[16];
    const float* lstm_w_hh= (const float*)d_in[17];
    const float* lstm_b_ih= (const float*)d_in[18];
    const float* lstm_b_hh= (const float*)d_in[19];
    const float* lin1_w   = (const float*)d_in[20];
    const float* lin1_b   = (const float*)d_in[21];
    const float* lin2_w   = (const float*)d_in[22];
    const float* lin2_b   = (const float*)d_in[23];
    float* y = (float*)d_out;

    const int N = NNODES, E = NEDGES;

    __half *We_h, *hedge_h, *nn2w_h;
    float *h, *agg, *m, *gi, *gh, *invdeg, *qstar, *hs, *cs;
    int *degi, *cnt;
    cudaGetSymbolAddress((void**)&We_h, g_We_h);
    cudaGetSymbolAddress((void**)&hedge_h, g_hedge_h);
    cudaGetSymbolAddress((void**)&nn2w_h, g_nn2w_h);
    cudaGetSymbolAddress((void**)&h, g_h);
    cudaGetSymbolAddress((void**)&agg, g_agg);
    cudaGetSymbolAddress((void**)&m, g_m);
    cudaGetSymbolAddress((void**)&gi, g_gi);
    cudaGetSymbolAddress((void**)&gh, g_gh);
    cudaGetSymbolAddress((void**)&invdeg, g_invdeg);
    cudaGetSymbolAddress((void**)&qstar, g_qstar);
    cudaGetSymbolAddress((void**)&hs, g_hs);
    cudaGetSymbolAddress((void**)&cs, g_cs);
    cudaGetSymbolAddress((void**)&degi, g_degi);
    cudaGetSymbolAddress((void**)&cnt, g_cnt);

    const int we_smem = 2 * 128 * WG_LDK * (int)sizeof(__half);  // ~68 KB
    cudaFuncSetAttribute(we_gemm_kernel, cudaFuncAttributeMaxDynamicSharedMemorySize, we_smem);

    // launches #1..#5, then we_gemm at #6 (ncu -s 5 -c 1 profiles it)
    f2h_kernel<<<(WE_COLS * EHID + 255) / 256, 256>>>(nn2_w, nn2w_h, WE_COLS * EHID);          // 1
    edge_mlp1_kernel<<<(E * EHID + 255) / 256, 256>>>(ea, nn1_w, nn1_b, E);                    // 2
    transpose_w_kernel<<<(256 * 128 + 255) / 256, 256>>>(lstm_w_ih, lstm_w_hh, lin1_w);        // 3
    cudaMemsetAsync(degi, 0, N * sizeof(int));                                                 // 4
    cudaMemsetAsync(cnt, 0, NG * sizeof(int));                                                 // 5
    {
        dim3 g(WE_COLS / 128, (E + 127) / 128);
        we_gemm_kernel<<<g, 256, we_smem>>>(hedge_h, nn2w_h, nn2_b, We_h, E);                  // 6
    }

    // ---- bookkeeping: degrees + sorted-batch segment starts ----
    count_deg_kernel<<<(E + 255) / 256, 256>>>(ei, E);
    count_batch_kernel<<<(N + 255) / 256, 256>>>(batch, N);
    invdeg_kernel<<<(N + 255) / 256, 256>>>(N);
    scan_kernel<<<1, NG>>>();

    // ---- lin0: h = relu(x @ lin0^T + b) ----
    {
        dim3 g(DIMV / BN, (N + BM - 1) / BM);
        gemm_kernel<<<g, 256>>>(x, lin0_w, lin0_b, nullptr, nullptr, h, N, DIMV, NFEAT, 1);
    }

    // ---- 3x NNConv + GRU ----
    for (int it = 0; it < 3; it++) {
        cudaMemsetAsync(agg, 0, (size_t)N * DIMV * sizeof(float));
        msg_kernel<<<(E + 7) / 8, 256>>>(ei, E);
        dim3 gm_(DIMV / BN, (N + BM - 1) / BM);
        gemm_kernel<<<gm_, 256>>>(h, root_w, conv_b, agg, invdeg, m, N, DIMV, DIMV, 1);
        dim3 gg(3 * DIMV / BN, (N + BM - 1) / BM);
        gemm_kernel<<<gg, 256>>>(m, gru_w_ih, gru_b_ih, nullptr, nullptr, gi, N, 3 * DIMV, DIMV, 0);
        gemm_kernel<<<gg, 256>>>(h, gru_w_hh, gru_b_hh, nullptr, nullptr, gh, N, 3 * DIMV, DIMV, 0);
        gru_kernel<<<(N * DIMV + 255) / 256, 256>>>(N);
    }

    // ---- Set2Set ----
    cudaMemsetAsync(qstar, 0, NG * 2 * DIMV * sizeof(float));
    cudaMemsetAsync(hs, 0, NG * DIMV * sizeof(float));
    cudaMemsetAsync(cs, 0, NG * DIMV * sizeof(float));
    for (int s = 0; s < 3; s++) {
        lstm_kernel<<<NG, 256>>>(lstm_b_ih, lstm_b_hh);
        attn_kernel<<<NG, 64>>>();
    }

    // ---- readout ----
    readout_kernel<<<NG, 64>>>(lin1_b, lin2_w, lin2_b, y);
}

// round 4
// speedup vs baseline: 6.0648x; 1.2979x over previous
#include <cuda_runtime.h>
#include <cuda_fp16.h>
#include <math.h>
#include <stdint.h>

#define DIMV   64
#define NG     512
#define NNODES 20000
#define NEDGES 60000
#define NFEAT  11
#define EHID   128
#define WE_COLS 4096   // DIM*DIM

// ---------------- scratch (__device__ globals; no allocations allowed) ----------------
__device__ __half g_We_h[(size_t)NEDGES * WE_COLS];   // 491 MB (fp16)
__device__ __half g_hedge_h[NEDGES * EHID];           // 15.4 MB (fp16)
__device__ __half g_nn2w_h[WE_COLS * EHID];           // 1 MB (fp16)
__device__ __half g_nodew_h[448 * 64];                // combined [root(64) | Wih(192) | Whh(192)] fp16
__device__ float g_h[NNODES * DIMV];                  // node state fp32
__device__ float g_agg[NNODES * DIMV];
__device__ float g_invdeg[NNODES];
__device__ int   g_degi[NNODES];
__device__ int   g_cnt[NG];
__device__ int   g_gstart[NG + 1];
__device__ float g_ebuf[NNODES];
__device__ float g_qstar[NG * 2 * DIMV];
__device__ float g_hs[NG * DIMV];
__device__ float g_cs[NG * DIMV];
// transposed small weights (coalesced GEMV reads)
__device__ float g_wihT[128 * 256];
__device__ float g_whhT[64 * 256];
__device__ float g_lin1T[128 * 64];

// ---------------- generic fp32 GEMM (lin0 only now) ----------------
#define BM 64
#define BN 64
#define BKK 16

__global__ void gemm_kernel(const float* __restrict__ A, const float* __restrict__ W,
                            const float* __restrict__ bias,
                            float* __restrict__ C, int M, int Nc, int K, int do_relu)
{
    __shared__ float As[BKK][BM];
    __shared__ float Ws[BKK][BN];

    const int bm = blockIdx.y * BM;
    const int bn = blockIdx.x * BN;
    const int tid = threadIdx.x;
    const int tm = (tid / 16) * 4;
    const int tn = (tid % 16) * 4;

    float acc[4][4];
#pragma unroll
    for (int i = 0; i < 4; i++)
#pragma unroll
        for (int j = 0; j < 4; j++) acc[i][j] = 0.f;

    for (int k0 = 0; k0 < K; k0 += BKK) {
#pragma unroll
        for (int r = 0; r < 4; r++) {
            int idx = tid + r * 256;
            int mm = idx / BKK, kk = idx % BKK;
            int gm = bm + mm, gk = k0 + kk;
            float v = 0.f;
            if (gm < M && gk < K) v = A[(size_t)gm * K + gk];
            As[kk][mm] = v;
        }
#pragma unroll
        for (int r = 0; r < 4; r++) {
            int idx = tid + r * 256;
            int nn = idx / BKK, kk = idx % BKK;
            int gn = bn + nn, gk = k0 + kk;
            float v = 0.f;
            if (gn < Nc && gk < K) v = W[(size_t)gn * K + gk];
            Ws[kk][nn] = v;
        }
        __syncthreads();

#pragma unroll
        for (int kk = 0; kk < BKK; kk++) {
            float a0 = As[kk][tm + 0], a1 = As[kk][tm + 1], a2 = As[kk][tm + 2], a3 = As[kk][tm + 3];
            float b0 = Ws[kk][tn + 0], b1 = Ws[kk][tn + 1], b2 = Ws[kk][tn + 2], b3 = Ws[kk][tn + 3];
            acc[0][0] += a0 * b0; acc[0][1] += a0 * b1; acc[0][2] += a0 * b2; acc[0][3] += a0 * b3;
            acc[1][0] += a1 * b0; acc[1][1] += a1 * b1; acc[1][2] += a1 * b2; acc[1][3] += a1 * b3;
            acc[2][0] += a2 * b0; acc[2][1] += a2 * b1; acc[2][2] += a2 * b2; acc[2][3] += a2 * b3;
            acc[3][0] += a3 * b0; acc[3][1] += a3 * b1; acc[3][2] += a3 * b2; acc[3][3] += a3 * b3;
        }
        __syncthreads();
    }

#pragma unroll
    for (int i = 0; i < 4; i++) {
        int gm = bm + tm + i;
        if (gm >= M) continue;
#pragma unroll
        for (int j = 0; j < 4; j++) {
            int gn = bn + tn + j;
            if (gn >= Nc) continue;
            float v = acc[i][j] + bias[gn];
            if (do_relu) v = fmaxf(v, 0.f);
            C[(size_t)gm * Nc + gn] = v;
        }
    }
}

// ---------------- conversions ----------------
__global__ void f2h_kernel(const float* __restrict__ src, __half* __restrict__ dst, int n)
{
    int i = blockIdx.x * blockDim.x + threadIdx.x;
    if (i < n) dst[i] = __float2half(src[i]);
}

__global__ void conv_nodew_kernel(const float* __restrict__ root_w,
                                  const float* __restrict__ wih, const float* __restrict__ whh)
{
    int i = blockIdx.x * blockDim.x + threadIdx.x;
    if (i >= 448 * 64) return;
    int row = i >> 6, k = i & 63;
    float v;
    if (row < 64)       v = root_w[row * 64 + k];
    else if (row < 256) v = wih[(row - 64) * 64 + k];
    else                v = whh[(row - 256) * 64 + k];
    g_nodew_h[i] = __float2half(v);
}

__global__ void transpose_w_kernel(const float* __restrict__ w_ih, const float* __restrict__ w_hh,
                                   const float* __restrict__ lin1_w)
{
    int i = blockIdx.x * blockDim.x + threadIdx.x;
    if (i < 256 * 128) { int r = i / 128, k = i % 128; g_wihT[k * 256 + r] = w_ih[i]; }
    if (i < 256 * 64)  { int r = i / 64,  k = i % 64;  g_whhT[k * 256 + r] = w_hh[i]; }
    if (i < 64 * 128)  { int r = i / 128, k = i % 128; g_lin1T[k * 64 + r] = lin1_w[i]; }
}

// ---------------- edge MLP layer 1 ----------------
__global__ void edge_mlp1_kernel(const float* __restrict__ ea,
                                 const float* __restrict__ nn1_w, const float* __restrict__ nn1_b,
                                 int E)
{
    int idx = blockIdx.x * blockDim.x + threadIdx.x;
    if (idx >= E * EHID) return;
    int e = idx / EHID, j = idx % EHID;
    float acc = nn1_b[j];
    const float* w = nn1_w + j * 5;
    const float* a = ea + e * 5;
#pragma unroll
    for (int k = 0; k < 5; k++) acc += a[k] * __ldg(&w[k]);
    g_hedge_h[idx] = __float2half(fmaxf(acc, 0.f));
}

// ---------------- mma helpers (patterns validated in R3) ----------------
__device__ __forceinline__ void mma16816(float c[4], const uint32_t a[4], uint32_t b0, uint32_t b1)
{
    asm volatile(
        "mma.sync.aligned.m16n8k16.row.col.f32.f16.f16.f32 "
        "{%0,%1,%2,%3}, {%4,%5,%6,%7}, {%8,%9}, {%0,%1,%2,%3};\n"
        : "+f"(c[0]), "+f"(c[1]), "+f"(c[2]), "+f"(c[3])
        : "r"(a[0]), "r"(a[1]), "r"(a[2]), "r"(a[3]), "r"(b0), "r"(b1));
}

// ---------------- big GEMM on tensor cores: We = hedge @ nn2^T + b ----------------
#define WG_PAD 8
#define WG_LDK (EHID + WG_PAD)

__global__ void __launch_bounds__(256) we_gemm_kernel(
    const __half* __restrict__ A, const __half* __restrict__ B,
    const float* __restrict__ bias, __half* __restrict__ C, int M)
{
    extern __shared__ __half smemh[];
    __half (*As)[WG_LDK] = (__half (*)[WG_LDK])smemh;
    __half (*Bs)[WG_LDK] = (__half (*)[WG_LDK])(smemh + 128 * WG_LDK);

    const int bm = blockIdx.y * 128;
    const int bn = blockIdx.x * 128;
    const int tid = threadIdx.x;
    const int warp = tid >> 5, lane = tid & 31;
    const int wm = (warp & 1) * 64;
    const int wn = (warp >> 1) * 32;

#pragma unroll
    for (int i = 0; i < 8; i++) {
        int idx = tid + i * 256;
        int row = idx >> 4, u = idx & 15;
        int gm = bm + row;
        uint32_t dst = (uint32_t)__cvta_generic_to_shared(&As[row][u * 8]);
        const void* src = A + (size_t)gm * EHID + u * 8;
        int sz = (gm < M) ? 16 : 0;
        asm volatile("cp.async.ca.shared.global [%0], [%1], 16, %2;\n"
                     :: "r"(dst), "l"(src), "r"(sz));
    }
#pragma unroll
    for (int i = 0; i < 8; i++) {
        int idx = tid + i * 256;
        int row = idx >> 4, u = idx & 15;
        uint32_t dst = (uint32_t)__cvta_generic_to_shared(&Bs[row][u * 8]);
        const void* src = B + (size_t)(bn + row) * EHID + u * 8;
        asm volatile("cp.async.ca.shared.global [%0], [%1], 16;\n"
                     :: "r"(dst), "l"(src));
    }
    asm volatile("cp.async.commit_group;\n" ::: "memory");
    asm volatile("cp.async.wait_group 0;\n" ::: "memory");
    __syncthreads();

    float c[4][4][4];
#pragma unroll
    for (int mt = 0; mt < 4; mt++)
#pragma unroll
        for (int nt = 0; nt < 4; nt++)
#pragma unroll
            for (int i = 0; i < 4; i++) c[mt][nt][i] = 0.f;

    const int g = lane >> 3, r = lane & 7;

#pragma unroll
    for (int k0 = 0; k0 < EHID; k0 += 16) {
        uint32_t af[4][4];
#pragma unroll
        for (int mt = 0; mt < 4; mt++) {
            uint32_t addr = (uint32_t)__cvta_generic_to_shared(
                &As[wm + mt * 16 + r + (g & 1) * 8][k0 + (g >> 1) * 8]);
            asm volatile("ldmatrix.sync.aligned.m8n8.x4.shared.b16 {%0,%1,%2,%3}, [%4];"
                         : "=r"(af[mt][0]), "=r"(af[mt][1]), "=r"(af[mt][2]), "=r"(af[mt][3])
                         : "r"(addr));
        }
        uint32_t bf[4][2];
#pragma unroll
        for (int p = 0; p < 2; p++) {
            uint32_t addr = (uint32_t)__cvta_generic_to_shared(
                &Bs[wn + p * 16 + r + (g >> 1) * 8][k0 + (g & 1) * 8]);
            uint32_t b0, b1, b2, b3;
            asm volatile("ldmatrix.sync.aligned.m8n8.x4.shared.b16 {%0,%1,%2,%3}, [%4];"
                         : "=r"(b0), "=r"(b1), "=r"(b2), "=r"(b3) : "r"(addr));
            bf[2 * p][0] = b0; bf[2 * p][1] = b1;
            bf[2 * p + 1][0] = b2; bf[2 * p + 1][1] = b3;
        }
#pragma unroll
        for (int mt = 0; mt < 4; mt++)
#pragma unroll
            for (int nt = 0; nt < 4; nt++)
                mma16816(c[mt][nt], af[mt], bf[nt][0], bf[nt][1]);
    }

#pragma unroll
    for (int mt = 0; mt < 4; mt++) {
        int row0 = bm + wm + mt * 16 + (lane >> 2);
#pragma unroll
        for (int nt = 0; nt < 4; nt++) {
            int gn = bn + wn + nt * 8 + 2 * (lane & 3);
            float b0 = bias[gn], b1 = bias[gn + 1];
            if (row0 < M) {
                __half2 h = __floats2half2_rn(c[mt][nt][0] + b0, c[mt][nt][1] + b1);
                *(__half2*)(C + (size_t)row0 * WE_COLS + gn) = h;
            }
            if (row0 + 8 < M) {
                __half2 h = __floats2half2_rn(c[mt][nt][2] + b0, c[mt][nt][3] + b1);
                *(__half2*)(C + (size_t)(row0 + 8) * WE_COLS + gn) = h;
            }
        }
    }
}

// ---------------- fused node update: m / GRU gates / new h, all on tensor cores ----------------
#define NU_LD 72   // padded halves per smem row (144 B, 16B-aligned, conflict-free for ldmatrix)

__device__ __forceinline__ void nu_lda(const __half (*sh)[NU_LD], int wm, int k0, int lane, uint32_t af[2][4])
{
    const int g = lane >> 3, r = lane & 7;
#pragma unroll
    for (int mt = 0; mt < 2; mt++) {
        uint32_t addr = (uint32_t)__cvta_generic_to_shared(
            &sh[wm + mt * 16 + r + (g & 1) * 8][k0 + (g >> 1) * 8]);
        asm volatile("ldmatrix.sync.aligned.m8n8.x4.shared.b16 {%0,%1,%2,%3}, [%4];"
                     : "=r"(af[mt][0]), "=r"(af[mt][1]), "=r"(af[mt][2]), "=r"(af[mt][3])
                     : "r"(addr));
    }
}

__device__ __forceinline__ void nu_ldb(const __half (*shW)[NU_LD], int rowbase, int wn, int k0, int lane,
                                       uint32_t bf[4][2])
{
    const int g = lane >> 3, r = lane & 7;
#pragma unroll
    for (int p = 0; p < 2; p++) {
        uint32_t addr = (uint32_t)__cvta_generic_to_shared(
            &shW[rowbase + wn + p * 16 + r + (g >> 1) * 8][k0 + (g & 1) * 8]);
        uint32_t b0, b1, b2, b3;
        asm volatile("ldmatrix.sync.aligned.m8n8.x4.shared.b16 {%0,%1,%2,%3}, [%4];"
                     : "=r"(b0), "=r"(b1), "=r"(b2), "=r"(b3) : "r"(addr));
        bf[2 * p][0] = b0; bf[2 * p][1] = b1;
        bf[2 * p + 1][0] = b2; bf[2 * p + 1][1] = b3;
    }
}

// accumulate c += A_tile(sh) @ W[rowbase..rowbase+63]^T  (K=64)
__device__ __forceinline__ void nu_mma(const __half (*shA)[NU_LD], const __half (*shW)[NU_LD],
                                       int rowbase, int wm, int wn, int lane, float c[2][4][4])
{
#pragma unroll
    for (int k0 = 0; k0 < 64; k0 += 16) {
        uint32_t af[2][4];
        nu_lda(shA, wm, k0, lane, af);
        uint32_t bf[4][2];
        nu_ldb(shW, rowbase, wn, k0, lane, bf);
#pragma unroll
        for (int mt = 0; mt < 2; mt++)
#pragma unroll
            for (int nt = 0; nt < 4; nt++)
                mma16816(c[mt][nt], af[mt], bf[nt][0], bf[nt][1]);
    }
}

__device__ __forceinline__ float sigmoidf_(float x) { return 1.f / (1.f + expf(-x)); }

__global__ void __launch_bounds__(256) node_update_kernel(
    const float* __restrict__ conv_b, const float* __restrict__ b_ih, const float* __restrict__ b_hh,
    int N)
{
    extern __shared__ __half sm_[];
    __half (*shW)[NU_LD] = (__half (*)[NU_LD])sm_;                     // 448 rows
    __half (*shH)[NU_LD] = (__half (*)[NU_LD])(sm_ + 448 * NU_LD);     // 128 rows
    __half (*shM)[NU_LD] = (__half (*)[NU_LD])(sm_ + (448 + 128) * NU_LD);

    const int bm = blockIdx.x * 128;
    const int tid = threadIdx.x;
    const int warp = tid >> 5, lane = tid & 31;
    const int wm = (warp & 3) * 32;   // 4 warps over 128 rows
    const int wn = (warp >> 2) * 32;  // 2 warps over 64 cols

    // load combined weights [448][64] via cp.async
#pragma unroll
    for (int i = 0; i < 14; i++) {
        int idx = tid + i * 256;          // 0..3583
        int row = idx >> 3, u = idx & 7;  // 8 x 16B chunks per 128B row
        uint32_t dst = (uint32_t)__cvta_generic_to_shared(&shW[row][u * 8]);
        const void* src = g_nodew_h + (size_t)row * 64 + u * 8;
        asm volatile("cp.async.ca.shared.global [%0], [%1], 16;\n" :: "r"(dst), "l"(src));
    }
    asm volatile("cp.async.commit_group;\n" ::: "memory");

    // load h tile fp32 -> fp16 smem
#pragma unroll
    for (int i = 0; i < 8; i++) {
        int idx = tid + i * 256;           // 0..2047
        int row = idx >> 4, u = idx & 15;  // 16 float4 per row
        int grow = bm + row;
        float4 v = make_float4(0.f, 0.f, 0.f, 0.f);
        if (grow < N) v = *(const float4*)(g_h + (size_t)grow * DIMV + u * 4);
        *(__half2*)(&shH[row][u * 4])     = __floats2half2_rn(v.x, v.y);
        *(__half2*)(&shH[row][u * 4 + 2]) = __floats2half2_rn(v.z, v.w);
    }
    asm volatile("cp.async.wait_group 0;\n" ::: "memory");
    __syncthreads();

    // ---- stage1: m = relu(agg*invdeg + h@root^T + conv_b) ----
    {
        float c[2][4][4];
#pragma unroll
        for (int mt = 0; mt < 2; mt++)
#pragma unroll
            for (int nt = 0; nt < 4; nt++)
#pragma unroll
                for (int i = 0; i < 4; i++) c[mt][nt][i] = 0.f;
        nu_mma(shH, shW, 0, wm, wn, lane, c);

#pragma unroll
        for (int mt = 0; mt < 2; mt++) {
            int lrow0 = wm + mt * 16 + (lane >> 2);
#pragma unroll
            for (int nt = 0; nt < 4; nt++) {
                int col = wn + nt * 8 + 2 * (lane & 3);
                float cb0 = conv_b[col], cb1 = conv_b[col + 1];
#pragma unroll
                for (int hrow = 0; hrow < 2; hrow++) {
                    int lrow = lrow0 + hrow * 8;
                    int grow = bm + lrow;
                    float a0 = 0.f, a1 = 0.f;
                    if (grow < N) {
                        float id = g_invdeg[grow];
                        float2 ag = *(const float2*)(g_agg + (size_t)grow * DIMV + col);
                        a0 = ag.x * id; a1 = ag.y * id;
                    }
                    float m0 = fmaxf(c[mt][nt][2 * hrow]     + a0 + cb0, 0.f);
                    float m1 = fmaxf(c[mt][nt][2 * hrow + 1] + a1 + cb1, 0.f);
                    *(__half2*)(&shM[lrow][col]) = __floats2half2_rn(m0, m1);
                }
            }
        }
    }
    __syncthreads();

    // ---- gate r (merged chains) ----
    float rfr[2][4][4];
#pragma unroll
    for (int mt = 0; mt < 2; mt++)
#pragma unroll
        for (int nt = 0; nt < 4; nt++)
#pragma unroll
            for (int i = 0; i < 4; i++) rfr[mt][nt][i] = 0.f;
    nu_mma(shM, shW, 64, wm, wn, lane, rfr);    // m @ Wih_r^T
    nu_mma(shH, shW, 256, wm, wn, lane, rfr);   // h @ Whh_r^T
#pragma unroll
    for (int mt = 0; mt < 2; mt++)
#pragma unroll
        for (int nt = 0; nt < 4; nt++) {
            int col = wn + nt * 8 + 2 * (lane & 3);
            float bb0 = b_ih[col] + b_hh[col];
            float bb1 = b_ih[col + 1] + b_hh[col + 1];
            rfr[mt][nt][0] = sigmoidf_(rfr[mt][nt][0] + bb0);
            rfr[mt][nt][1] = sigmoidf_(rfr[mt][nt][1] + bb1);
            rfr[mt][nt][2] = sigmoidf_(rfr[mt][nt][2] + bb0);
            rfr[mt][nt][3] = sigmoidf_(rfr[mt][nt][3] + bb1);
        }

    // ---- gate n: n = tanh(in + b_in + r*(hn + b_hn)) ----
    float nfr[2][4][4];
    {
        float cin[2][4][4], chn[2][4][4];
#pragma unroll
        for (int mt = 0; mt < 2; mt++)
#pragma unroll
            for (int nt = 0; nt < 4; nt++)
#pragma unroll
                for (int i = 0; i < 4; i++) { cin[mt][nt][i] = 0.f; chn[mt][nt][i] = 0.f; }
        nu_mma(shM, shW, 64 + 128, wm, wn, lane, cin);   // m @ Wih_n^T
        nu_mma(shH, shW, 256 + 128, wm, wn, lane, chn);  // h @ Whh_n^T
#pragma unroll
        for (int mt = 0; mt < 2; mt++)
#pragma unroll
            for (int nt = 0; nt < 4; nt++) {
                int col = wn + nt * 8 + 2 * (lane & 3);
                float bi0 = b_ih[128 + col], bi1 = b_ih[128 + col + 1];
                float bh0 = b_hh[128 + col], bh1 = b_hh[128 + col + 1];
                nfr[mt][nt][0] = tanhf(cin[mt][nt][0] + bi0 + rfr[mt][nt][0] * (chn[mt][nt][0] + bh0));
                nfr[mt][nt][1] = tanhf(cin[mt][nt][1] + bi1 + rfr[mt][nt][1] * (chn[mt][nt][1] + bh1));
                nfr[mt][nt][2] = tanhf(cin[mt][nt][2] + bi0 + rfr[mt][nt][2] * (chn[mt][nt][2] + bh0));
                nfr[mt][nt][3] = tanhf(cin[mt][nt][3] + bi1 + rfr[mt][nt][3] * (chn[mt][nt][3] + bh1));
            }
    }

    // ---- gate z (merged) + final h' = (1-z)*n + z*h_old ----
    {
        float cz[2][4][4];
#pragma unroll
        for (int mt = 0; mt < 2; mt++)
#pragma unroll
            for (int nt = 0; nt < 4; nt++)
#pragma unroll
                for (int i = 0; i < 4; i++) cz[mt][nt][i] = 0.f;
        nu_mma(shM, shW, 64 + 64, wm, wn, lane, cz);
        nu_mma(shH, shW, 256 + 64, wm, wn, lane, cz);
#pragma unroll
        for (int mt = 0; mt < 2; mt++) {
            int lrow0 = wm + mt * 16 + (lane >> 2);
#pragma unroll
            for (int nt = 0; nt < 4; nt++) {
                int col = wn + nt * 8 + 2 * (lane & 3);
                float bb0 = b_ih[64 + col] + b_hh[64 + col];
                float bb1 = b_ih[64 + col + 1] + b_hh[64 + col + 1];
#pragma unroll
                for (int hrow = 0; hrow < 2; hrow++) {
                    int grow = bm + lrow0 + hrow * 8;
                    if (grow >= N) continue;
                    float z0 = sigmoidf_(cz[mt][nt][2 * hrow]     + bb0);
                    float z1 = sigmoidf_(cz[mt][nt][2 * hrow + 1] + bb1);
                    float2 ho = *(const float2*)(g_h + (size_t)grow * DIMV + col);
                    float2 hn_;
                    hn_.x = (1.f - z0) * nfr[mt][nt][2 * hrow]     + z0 * ho.x;
                    hn_.y = (1.f - z1) * nfr[mt][nt][2 * hrow + 1] + z1 * ho.y;
                    *(float2*)(g_h + (size_t)grow * DIMV + col) = hn_;
                }
            }
        }
    }
}

// ---------------- degree / batch bookkeeping ----------------
__global__ void count_deg_kernel(const int* __restrict__ ei, int E)
{
    int e = blockIdx.x * blockDim.x + threadIdx.x;
    if (e < E) atomicAdd(&g_degi[ei[E + e]], 1);
}

__global__ void count_batch_kernel(const int* __restrict__ batch, int N)
{
    int i = blockIdx.x * blockDim.x + threadIdx.x;
    if (i < N) atomicAdd(&g_cnt[batch[i]], 1);
}

__global__ void invdeg_kernel(int N)
{
    int i = blockIdx.x * blockDim.x + threadIdx.x;
    if (i < N) g_invdeg[i] = 1.f / fmaxf((float)g_degi[i], 1.f);
}

__global__ void scan_kernel()
{
    __shared__ int s[NG];
    int t = threadIdx.x;
    s[t] = g_cnt[t];
    __syncthreads();
    for (int off = 1; off < NG; off <<= 1) {
        int v = (t >= off) ? s[t - off] : 0;
        __syncthreads();
        s[t] += v;
        __syncthreads();
    }
    if (t == 0) g_gstart[0] = 0;
    g_gstart[t + 1] = s[t];
}

// ---------------- per-edge message + scatter ----------------
__global__ void msg_kernel(const int* __restrict__ ei, int E)
{
    const int w    = threadIdx.x >> 5;
    const int lane = threadIdx.x & 31;
    const int e    = blockIdx.x * 8 + w;
    __shared__ float s_a[8][DIMV];

    if (e >= E) return;
    int src = ei[e];
    int dst = ei[E + e];
    s_a[w][lane]      = g_h[src * DIMV + lane];
    s_a[w][lane + 32] = g_h[src * DIMV + lane + 32];
    __syncwarp();

    const __half2* __restrict__ wp = (const __half2*)(g_We_h + (size_t)e * WE_COLS) + lane;
    float accx = 0.f, accy = 0.f;
#pragma unroll
    for (int i = 0; i < DIMV; i++) {
        float a = s_a[w][i];
        float2 wv = __half22float2(wp[i * 32]);
        accx = fmaf(a, wv.x, accx);
        accy = fmaf(a, wv.y, accy);
    }
    atomicAdd(&g_agg[dst * DIMV + 2 * lane],     accx);
    atomicAdd(&g_agg[dst * DIMV + 2 * lane + 1], accy);
}

// ---------------- Set2Set LSTM step ----------------
__global__ void lstm_kernel(const float* __restrict__ b_ih, const float* __restrict__ b_hh)
{
    int b = blockIdx.x, t = threadIdx.x;
    __shared__ float qs[2 * DIMV];
    __shared__ float hsh[DIMV];
    __shared__ float gates[4 * DIMV];
    if (t < 128) qs[t] = g_qstar[b * 128 + t];
    if (t < 64)  hsh[t] = g_hs[b * 64 + t];
    __syncthreads();

    float acc = b_ih[t] + b_hh[t];
#pragma unroll 8
    for (int k = 0; k < 128; k++) acc += qs[k] * g_wihT[k * 256 + t];
#pragma unroll 8
    for (int k = 0; k < 64; k++)  acc += hsh[k] * g_whhT[k * 256 + t];
    gates[t] = acc;
    __syncthreads();

    if (t < 64) {
        float i = 1.f / (1.f + expf(-gates[t]));
        float f = 1.f / (1.f + expf(-gates[64 + t]));
        float g = tanhf(gates[128 + t]);
        float o = 1.f / (1.f + expf(-gates[192 + t]));
        float c = f * g_cs[b * 64 + t] + i * g;
        g_cs[b * 64 + t] = c;
        g_hs[b * 64 + t] = o * tanhf(c);
    }
}

// ---------------- Set2Set attention ----------------
__global__ void attn_kernel()
{
    int b = blockIdx.x, t = threadIdx.x;
    int s = g_gstart[b], e_end = g_gstart[b + 1];
    __shared__ float q[DIMV];
    __shared__ float red[DIMV];
    q[t] = g_hs[b * DIMV + t];
    __syncthreads();

    float lmax = -1e30f;
    for (int n = s + t; n < e_end; n += 64) {
        const float* row = g_h + (size_t)n * DIMV;
        float acc = 0.f;
#pragma unroll 8
        for (int i = 0; i < DIMV; i++) acc += row[i] * q[i];
        g_ebuf[n] = acc;
        lmax = fmaxf(lmax, acc);
    }
    red[t] = lmax; __syncthreads();
    for (int st = 32; st > 0; st >>= 1) { if (t < st) red[t] = fmaxf(red[t], red[t + st]); __syncthreads(); }
    float gmax = red[0];
    __syncthreads();

    float lsum = 0.f;
    for (int n = s + t; n < e_end; n += 64) {
        float a = expf(g_ebuf[n] - gmax);
        g_ebuf[n] = a;
        lsum += a;
    }
    red[t] = lsum; __syncthreads();
    for (int st = 32; st > 0; st >>= 1) { if (t < st) red[t] += red[t + st]; __syncthreads(); }
    float S = red[0];
    __syncthreads();

    float r = 0.f;
    for (int n = s; n < e_end; n++) r += g_ebuf[n] * g_h[(size_t)n * DIMV + t];

    g_qstar[b * 128 + t] = q[t];
    g_qstar[b * 128 + 64 + t] = (e_end > s) ? (r / S) : 0.f;
}

// ---------------- readout ----------------
__global__ void readout_kernel(const float* __restrict__ lin1_b,
                               const float* __restrict__ lin2_w, const float* __restrict__ lin2_b,
                               float* __restrict__ y)
{
    int b = blockIdx.x, t = threadIdx.x;
    __shared__ float q[128];
    __shared__ float red[64];
    q[t] = g_qstar[b * 128 + t];
    q[64 + t] = g_qstar[b * 128 + 64 + t];
    __syncthreads();

    float acc = lin1_b[t];
#pragma unroll 8
    for (int k = 0; k < 128; k++) acc += q[k] * g_lin1T[k * 64 + t];
    float z = fmaxf(acc, 0.f);

    red[t] = z * lin2_w[t];
    __syncthreads();
    for (int st = 32; st > 0; st >>= 1) { if (t < st) red[t] += red[t + st]; __syncthreads(); }
    if (t == 0) y[b] = red[0] + lin2_b[0];
}

// ======================================================================================
extern "C" void kernel_launch(void* const* d_in, const int* in_sizes, int n_in,
                              void* d_out, int out_size)
{
    const float* x        = (const float*)d_in[0];
    const int*   ei       = (const int*)  d_in[1];
    const float* ea       = (const float*)d_in[2];
    const int*   batch    = (const int*)  d_in[3];
    const float* lin0_w   = (const float*)d_in[4];
    const float* lin0_b   = (const float*)d_in[5];
    const float* nn1_w    = (const float*)d_in[6];
    const float* nn1_b    = (const float*)d_in[7];
    const float* nn2_w    = (const float*)d_in[8];
    const float* nn2_b    = (const float*)d_in[9];
    const float* root_w   = (const float*)d_in[10];
    const float* conv_b   = (const float*)d_in[11];
    const float* gru_w_ih = (const float*)d_in[12];
    const float* gru_w_hh = (const float*)d_in[13];
    const float* gru_b_ih = (const float*)d_in[14];
    const float* gru_b_hh = (const float*)d_in[15];
    const float* lstm_w_ih= (const float*)d_in[16];
    const float* lstm_w_hh= (const float*)d_in[17];
    const float* lstm_b_ih= (const float*)d_in[18];
    const float* lstm_b_hh= (const float*)d_in[19];
    const float* lin1_b   = (const float*)d_in[21];
    const float* lin1_w   = (const float*)d_in[20];
    const float* lin2_w   = (const float*)d_in[22];
    const float* lin2_b   = (const float*)d_in[23];
    float* y = (float*)d_out;

    const int N = NNODES, E = NEDGES;

    __half *We_h, *hedge_h, *nn2w_h;
    float *h, *agg, *qstar, *hs, *cs;
    int *degi, *cnt;
    cudaGetSymbolAddress((void**)&We_h, g_We_h);
    cudaGetSymbolAddress((void**)&hedge_h, g_hedge_h);
    cudaGetSymbolAddress((void**)&nn2w_h, g_nn2w_h);
    cudaGetSymbolAddress((void**)&h, g_h);
    cudaGetSymbolAddress((void**)&agg, g_agg);
    cudaGetSymbolAddress((void**)&qstar, g_qstar);
    cudaGetSymbolAddress((void**)&hs, g_hs);
    cudaGetSymbolAddress((void**)&cs, g_cs);
    cudaGetSymbolAddress((void**)&degi, g_degi);
    cudaGetSymbolAddress((void**)&cnt, g_cnt);

    const int we_smem = 2 * 128 * WG_LDK * (int)sizeof(__half);
    cudaFuncSetAttribute(we_gemm_kernel, cudaFuncAttributeMaxDynamicSharedMemorySize, we_smem);
    const int nu_smem = (448 + 128 + 128) * NU_LD * (int)sizeof(__half);   // ~101 KB
    cudaFuncSetAttribute(node_update_kernel, cudaFuncAttributeMaxDynamicSharedMemorySize, nu_smem);

    f2h_kernel<<<(WE_COLS * EHID + 255) / 256, 256>>>(nn2_w, nn2w_h, WE_COLS * EHID);      // 1
    conv_nodew_kernel<<<(448 * 64 + 255) / 256, 256>>>(root_w, gru_w_ih, gru_w_hh);        // 2
    edge_mlp1_kernel<<<(E * EHID + 255) / 256, 256>>>(ea, nn1_w, nn1_b, E);                // 3
    transpose_w_kernel<<<(256 * 128 + 255) / 256, 256>>>(lstm_w_ih, lstm_w_hh, lin1_w);    // 4
    cudaMemsetAsync(degi, 0, N * sizeof(int));                                             // 5
    {
        dim3 g(WE_COLS / 128, (E + 127) / 128);
        we_gemm_kernel<<<g, 256, we_smem>>>(hedge_h, nn2w_h, nn2_b, We_h, E);              // 6 (profiled)
    }

    cudaMemsetAsync(cnt, 0, NG * sizeof(int));
    count_deg_kernel<<<(E + 255) / 256, 256>>>(ei, E);
    count_batch_kernel<<<(N + 255) / 256, 256>>>(batch, N);
    invdeg_kernel<<<(N + 255) / 256, 256>>>(N);
    scan_kernel<<<1, NG>>>();

    // lin0: h = relu(x @ lin0^T + b)
    {
        dim3 g(DIMV / BN, (N + BM - 1) / BM);
        gemm_kernel<<<g, 256>>>(x, lin0_w, lin0_b, h, N, DIMV, NFEAT, 1);
    }

    // 3x NNConv + GRU (fused node update)
    for (int it = 0; it < 3; it++) {
        cudaMemsetAsync(agg, 0, (size_t)N * DIMV * sizeof(float));
        msg_kernel<<<(E + 7) / 8, 256>>>(ei, E);
        node_update_kernel<<<(N + 127) / 128, 256, nu_smem>>>(conv_b, gru_b_ih, gru_b_hh, N);
    }

    // Set2Set
    cudaMemsetAsync(qstar, 0, NG * 2 * DIMV * sizeof(float));
    cudaMemsetAsync(hs, 0, NG * DIMV * sizeof(float));
    cudaMemsetAsync(cs, 0, NG * DIMV * sizeof(float));
    for (int s = 0; s < 3; s++) {
        lstm_kernel<<<NG, 256>>>(lstm_b_ih, lstm_b_hh);
        attn_kernel<<<NG, 64>>>();
    }

    readout_kernel<<<NG, 64>>>(lin1_b, lin2_w, lin2_b, y);
}